// round 11
// baseline (speedup 1.0000x reference)
#include <cuda_runtime.h>

#define IN_OP   64
#define IN_MAC  32
#define OUTF    128
#define HEADS   4
#define DK      32
#define ATT     65
#define N_OP_MAX   50000
#define N_MAC_MAX  2000
#define CAP_OP  32
#define CAP_MAC 320
#define EPS     1e-6f
#define MAC_BLOCKS 64
#define OM_CHUNK   8192
#define SM_CHUNK   1024
// XOR swizzle for the transposed weight tile: kills the 32-way STS conflict
// (4-way instead), keeps 16B alignment for ulonglong2 loads, zero smem overhead.
#define SWZ(k, j) ((j) ^ (((k) * 4) & 127))

// ---------------- scratch (device globals; no runtime allocation) ----------------
// unified z: op rows [0, N_OP_MAX), mac rows [N_OP_MAX, N_OP_MAX+N_MAC_MAX)
__device__ __align__(16) float g_z[(N_OP_MAX + N_MAC_MAX) * OUTF];

__device__ __align__(16) float g_asrc_seq[N_OP_MAX  * HEADS];
__device__ __align__(16) float g_adst_seq[N_OP_MAX  * HEADS];
__device__ __align__(16) float g_asrc_om [N_OP_MAX  * HEADS];
__device__ __align__(16) float g_adst_mo [N_OP_MAX  * HEADS];
__device__ __align__(16) float g_asrc_mo [N_MAC_MAX * HEADS];
__device__ __align__(16) float g_adst_om [N_MAC_MAX * HEADS];

// compact per-dst edge buckets: {src, feat_bits}
__device__ __align__(16) int2 g_eb_seq[N_OP_MAX  * CAP_OP];
__device__ __align__(16) int2 g_eb_mo [N_OP_MAX  * CAP_OP];
__device__ __align__(16) int2 g_eb_om [N_MAC_MAX * CAP_MAC];

// degree counters (zeroed by one memset)
#define DEG_SEQ_OFF 0
#define DEG_MO_OFF  N_OP_MAX
#define DEG_OM_OFF  (2 * N_OP_MAX)
#define DEG_TOT     (2 * N_OP_MAX + N_MAC_MAX)
__device__ __align__(16) int g_deg[DEG_TOT];

// ---------------- helpers ----------------
__device__ __forceinline__ float wallred(float v) {
#pragma unroll
    for (int o = 16; o > 0; o >>= 1) v += __shfl_xor_sync(0xffffffffu, v, o);
    return v;
}
__device__ __forceinline__ float wredsum(float v) {
#pragma unroll
    for (int o = 16; o > 0; o >>= 1) v += __shfl_down_sync(0xffffffffu, v, o);
    return v;
}
__device__ __forceinline__ float red8(float v) {
    v += __shfl_xor_sync(0xffffffffu, v, 1);
    v += __shfl_xor_sync(0xffffffffu, v, 2);
    v += __shfl_xor_sync(0xffffffffu, v, 4);
    return v;
}
// leaky_relu(0.2) -> clip(+-20) -> exp
__device__ __forceinline__ float lrexp(float v) {
    v = v > 0.f ? v : 0.2f * v;
    v = fminf(fmaxf(v, -20.f), 20.f);
    return __expf(v);
}
// packed f32x2 (Blackwell FFMA2)
__device__ __forceinline__ unsigned long long pack2(float lo, float hi) {
    unsigned long long r;
    asm("mov.b64 %0, {%1, %2};" : "=l"(r) : "f"(lo), "f"(hi));
    return r;
}
__device__ __forceinline__ void unpack2(unsigned long long v, float& lo, float& hi) {
    asm("mov.b64 {%0, %1}, %2;" : "=f"(lo), "=f"(hi) : "l"(v));
}
__device__ __forceinline__ void ffma2(unsigned long long& d, unsigned long long a,
                                      unsigned long long b) {
    asm("fma.rn.f32x2 %0, %1, %2, %0;" : "+l"(d) : "l"(a), "l"(b));
}

// ===================== prep kernel blocks =====================

// 32-node tile; h stored PRE-DUPLICATED as float2 (h,h) so the FFMA2 loop reads
// broadcast ulonglong2 directly -- no pack movs in the hot loop.
__device__ void proj_op_block(int bid, int prj_blocks,
                              const float* __restrict__ h, const float* __restrict__ W,
                              const float* __restrict__ bias,
                              const float* __restrict__ att_seq, const float* __restrict__ att_om,
                              const float* __restrict__ att_mo, int n,
                              float* __restrict__ z,
                              float* __restrict__ asrc_seq, float* __restrict__ adst_seq,
                              float* __restrict__ asrc_om,  float* __restrict__ adst_mo,
                              float* pool)
{
    float* sW  = pool;                 // 8192 floats, transposed+swizzled: sW[k*128 + SWZ(k,j)]
    float* sh2 = pool + IN_OP * OUTF;  // 4096 floats = 2048 float2 (32 nodes x 64 k, duplicated)
    int tid = threadIdx.x;
    int warp = tid >> 5, lane = tid & 31;
    // vectorized W load + swizzled transpose (4 consecutive k within one j row)
    for (int i = tid * 4; i < IN_OP * OUTF; i += 1024) {
        float4 wv = *(const float4*)(W + i);
        int j = i >> 6, k = i & 63;
        sW[(k + 0) * OUTF + SWZ(k + 0, j)] = wv.x;
        sW[(k + 1) * OUTF + SWZ(k + 1, j)] = wv.y;
        sW[(k + 2) * OUTF + SWZ(k + 2, j)] = wv.z;
        sW[(k + 3) * OUTF + SWZ(k + 3, j)] = wv.w;
    }
    int f0 = lane * 4;
    int head = lane >> 3;
    int dk = f0 & 31;
    float a_s1[4], a_d1[4], a_s3[4], a_d4[4];
#pragma unroll
    for (int i = 0; i < 4; i++) {
        a_s1[i] = att_seq[head * ATT + dk + i];
        a_d1[i] = att_seq[head * ATT + DK + dk + i];
        a_s3[i] = att_om [head * ATT + dk + i];
        a_d4[i] = att_mo [head * ATT + DK + dk + i];
    }
    float4 bj = *(const float4*)(bias + f0);
    unsigned long long bj0 = pack2(bj.x, bj.y), bj1 = pack2(bj.z, bj.w);

    for (int n0 = bid * 32; n0 < n; n0 += prj_blocks * 32) {
        int cnt = min(n - n0, 32);
        __syncthreads();
        // duplicated h load (float4 in, 4x float2 out)
        for (int i = tid * 4; i < cnt * IN_OP; i += 1024) {
            float4 hv = *(const float4*)(h + (size_t)n0 * IN_OP + i);
            float2* p = (float2*)sh2 + i;
            p[0] = make_float2(hv.x, hv.x);
            p[1] = make_float2(hv.y, hv.y);
            p[2] = make_float2(hv.z, hv.z);
            p[3] = make_float2(hv.w, hv.w);
        }
        __syncthreads();
        unsigned long long acc[4][2];
#pragma unroll
        for (int r = 0; r < 4; r++) { acc[r][0] = bj0; acc[r][1] = bj1; }
        int base = warp * 4;
#pragma unroll 2
        for (int k4 = 0; k4 < IN_OP; k4 += 4) {
            // swizzled offset is a row-constant multiple of 4 -> 16B-aligned, conflict-free
            ulonglong2 w0 = *(const ulonglong2*)(sW + (k4 + 0) * OUTF + SWZ(k4 + 0, f0));
            ulonglong2 w1 = *(const ulonglong2*)(sW + (k4 + 1) * OUTF + SWZ(k4 + 1, f0));
            ulonglong2 w2 = *(const ulonglong2*)(sW + (k4 + 2) * OUTF + SWZ(k4 + 2, f0));
            ulonglong2 w3 = *(const ulonglong2*)(sW + (k4 + 3) * OUTF + SWZ(k4 + 3, f0));
#pragma unroll
            for (int r = 0; r < 4; r++) {
                const ulonglong2* hp =
                    (const ulonglong2*)(sh2 + ((base + r) * IN_OP + k4) * 2);
                ulonglong2 h01 = hp[0];   // {(h_k,h_k),(h_k1,h_k1)} broadcast
                ulonglong2 h23 = hp[1];
                ffma2(acc[r][0], h01.x, w0.x); ffma2(acc[r][1], h01.x, w0.y);
                ffma2(acc[r][0], h01.y, w1.x); ffma2(acc[r][1], h01.y, w1.y);
                ffma2(acc[r][0], h23.x, w2.x); ffma2(acc[r][1], h23.x, w2.y);
                ffma2(acc[r][0], h23.y, w3.x); ffma2(acc[r][1], h23.y, w3.y);
            }
        }
#pragma unroll
        for (int r = 0; r < 4; r++) {
            int node = n0 + base + r;
            if (base + r >= cnt) break;   // uniform across warp
            float4 zz;
            unpack2(acc[r][0], zz.x, zz.y);
            unpack2(acc[r][1], zz.z, zz.w);
            // SWZ is an involution: each thread accumulated its own logical cols f0..f0+3
            *(float4*)(z + (size_t)node * OUTF + f0) = zz;
            float p1 = zz.x * a_s1[0] + zz.y * a_s1[1] + zz.z * a_s1[2] + zz.w * a_s1[3];
            float p2 = zz.x * a_d1[0] + zz.y * a_d1[1] + zz.z * a_d1[2] + zz.w * a_d1[3];
            float p3 = zz.x * a_s3[0] + zz.y * a_s3[1] + zz.z * a_s3[2] + zz.w * a_s3[3];
            float p4 = zz.x * a_d4[0] + zz.y * a_d4[1] + zz.z * a_d4[2] + zz.w * a_d4[3];
            p1 = red8(p1); p2 = red8(p2); p3 = red8(p3); p4 = red8(p4);
            if ((lane & 7) == 0) {
                asrc_seq[node * HEADS + head] = p1;
                adst_seq[node * HEADS + head] = p2;
                asrc_om [node * HEADS + head] = p3;
                adst_mo [node * HEADS + head] = p4;
            }
        }
    }
}

__device__ void proj_mac_block(int mbid, const float* __restrict__ h, const float* __restrict__ W,
                               const float* __restrict__ bias,
                               const float* __restrict__ att_mo, const float* __restrict__ att_om,
                               int n, float* __restrict__ z,   // z already offset to mac region
                               float* __restrict__ asrc_mo, float* __restrict__ adst_om,
                               float* pool)
{
    float* sW = pool;                  // 4096 floats, swizzled
    float* sh = pool + IN_MAC * OUTF;  // 64 floats (2 nodes x 32)
    int tid = threadIdx.x;
    for (int i = tid * 4; i < IN_MAC * OUTF; i += 1024) {
        float4 wv = *(const float4*)(W + i);
        int j = i >> 5, k = i & 31;
        sW[(k + 0) * OUTF + SWZ(k + 0, j)] = wv.x;
        sW[(k + 1) * OUTF + SWZ(k + 1, j)] = wv.y;
        sW[(k + 2) * OUTF + SWZ(k + 2, j)] = wv.z;
        sW[(k + 3) * OUTF + SWZ(k + 3, j)] = wv.w;
    }
    int wg = tid >> 7, wtid = tid & 127;
    int head = wtid >> 5, lane = wtid & 31;
    float a1 = att_mo[head * ATT + lane];
    float a2 = att_om[head * ATT + DK + lane];
    float bj = bias[wtid];
    for (int n0 = mbid * 2; n0 < n; n0 += MAC_BLOCKS * 2) {
        int cnt = min(n - n0, 2);
        __syncthreads();
        for (int i = tid; i < cnt * IN_MAC; i += 256) sh[i] = h[(size_t)n0 * IN_MAC + i];
        __syncthreads();
        int node = n0 + wg;
        if (node < n) {
            float zz = bj;
#pragma unroll
            for (int k = 0; k < IN_MAC; k++)
                zz += sh[wg * IN_MAC + k] * sW[k * OUTF + SWZ(k, wtid)];
            z[(size_t)node * OUTF + wtid] = zz;
            float s1 = wredsum(zz * a1);
            float s2 = wredsum(zz * a2);
            if (lane == 0) {
                asrc_mo[node * HEADS + head] = s1;
                adst_om[node * HEADS + head] = s2;
            }
        }
    }
}

// CTA-aggregated om bucketing: per-block smem counts -> one global atomic per
// distinct dst per block -> smem-slot scatter.
__device__ void bucket_om_block(int ob, int E, int nmac,
                                const int* __restrict__ src, const int* __restrict__ dst,
                                const float* __restrict__ feat,
                                int* __restrict__ deg, int2* __restrict__ eb,
                                float* pool)
{
    int* scnt  = (int*)pool;           // nmac counters
    int* sbase = (int*)pool + N_MAC_MAX;
    int tid = threadIdx.x;
    int e0 = ob * OM_CHUNK;
    int e1 = min(e0 + OM_CHUNK, E);
    for (int i = tid; i < nmac; i += 256) scnt[i] = 0;
    __syncthreads();
    for (int e = e0 + tid; e < e1; e += 256) atomicAdd(scnt + dst[e], 1);
    __syncthreads();
    for (int i = tid; i < nmac; i += 256) {
        int c = scnt[i];
        sbase[i] = c ? atomicAdd(deg + i, c) : 0;
        scnt[i] = 0;
    }
    __syncthreads();
    for (int e = e0 + tid; e < e1; e += 256) {
        int d = dst[e];
        int slot = sbase[d] + atomicAdd(scnt + d, 1);
        if (slot < CAP_MAC)
            eb[(size_t)d * CAP_MAC + slot] = make_int2(src[e], __float_as_int(feat[e]));
    }
}

// seq+mo edges: op dsts (50k) -> low contention, direct atomics, 4 edges/thread
__device__ void bucket_sm_block(int sb, int Ea, int Eb,
                                const int* __restrict__ sa, const int* __restrict__ da,
                                const float* __restrict__ fa,
                                const int* __restrict__ sb_, const int* __restrict__ db,
                                const float* __restrict__ fb,
                                int* __restrict__ dega, int2* __restrict__ eba,
                                int* __restrict__ degb, int2* __restrict__ ebb)
{
    int tid = threadIdx.x;
#pragma unroll
    for (int r = 0; r < 4; r++) {
        int e = sb * SM_CHUNK + r * 256 + tid;
        if (e < Ea) {
            int s = sa[e], d = da[e];
            float f = fa[e];
            int slot = atomicAdd(dega + d, 1);
            if (slot < CAP_OP) eba[(size_t)d * CAP_OP + slot] = make_int2(s, __float_as_int(f));
        } else if (e < Ea + Eb) {
            int ee = e - Ea;
            int s = sb_[ee], d = db[ee];
            float f = fb[ee];
            int slot = atomicAdd(degb + d, 1);
            if (slot < CAP_OP) ebb[(size_t)d * CAP_OP + slot] = make_int2(s, __float_as_int(f));
        }
    }
}

__global__ __launch_bounds__(256) void k_prep(
    const float* h_op, const float* W_op_w, const float* W_op_b,
    const float* h_mac, const float* W_mac_w, const float* W_mac_b,
    const float* att_seq, const float* att_om, const float* att_mo,
    int nop, int nmac, int prj_blocks,
    int Eseq, int Emo, int Eom, int om_blocks,
    const int* seq_src, const int* seq_dst, const float* feat_seq,
    const int* mo_src,  const int* mo_dst,  const float* feat_mo,
    const int* om_src,  const int* om_dst,  const float* feat_om,
    float* z, float* z_mac,
    float* asrc_seq, float* adst_seq, float* asrc_om, float* adst_mo,
    float* asrc_mo, float* adst_om,
    int* deg_seq, int2* eb_seq, int* deg_mo, int2* eb_mo, int* deg_om, int2* eb_om)
{
    __shared__ __align__(16) float pool[IN_OP * OUTF + 32 * IN_OP * 2];  // 48 KB
    int bid = blockIdx.x;
    if (bid < prj_blocks) {
        proj_op_block(bid, prj_blocks, h_op, W_op_w, W_op_b, att_seq, att_om, att_mo, nop,
                      z, asrc_seq, adst_seq, asrc_om, adst_mo, pool);
    } else if (bid < prj_blocks + MAC_BLOCKS) {
        proj_mac_block(bid - prj_blocks, h_mac, W_mac_w, W_mac_b, att_mo, att_om, nmac,
                       z_mac, asrc_mo, adst_om, pool);
    } else if (bid < prj_blocks + MAC_BLOCKS + om_blocks) {
        bucket_om_block(bid - prj_blocks - MAC_BLOCKS, Eom, nmac,
                        om_src, om_dst, feat_om, deg_om, eb_om, pool);
    } else {
        bucket_sm_block(bid - prj_blocks - MAC_BLOCKS - om_blocks, Eseq, Emo,
                        seq_src, seq_dst, feat_seq,
                        mo_src, mo_dst, feat_mo,
                        deg_seq, eb_seq, deg_mo, eb_mo);
    }
}

// diagnostic spacer: shifts ncu's fixed capture index onto k_prep
__global__ void k_nop() {}

// ===================== final kernel =====================

// per-warp gather for one edge group of an op node; returns normalized contribution.
// soff holds precomputed row offsets (src*OUTF) -> 32-bit add in hot loop, no IMAD.wide.
__device__ __forceinline__ float4 gat_group(int d, const int* __restrict__ deg,
                                            const int2* __restrict__ eb,
                                            const float* __restrict__ asrc,
                                            const float* __restrict__ adst,
                                            const float* __restrict__ att,
                                            const float* __restrict__ z,
                                            float* salpha, int* soff,
                                            int lane, int head, int f0)
{
    float4 res = make_float4(0.f, 0.f, 0.f, 0.f);
    int cs = min(deg[d], CAP_OP);
    if (cs == 0) return res;
    float4 ad4 = *(const float4*)(adst + (size_t)d * HEADS);
    float af0 = att[2 * DK], af1 = att[ATT + 2 * DK], af2 = att[2 * ATT + 2 * DK],
          af3 = att[3 * ATT + 2 * DK];
    if (lane < cs) {
        int2 ed = eb[(size_t)d * CAP_OP + lane];
        float4 as = *(const float4*)(asrc + (size_t)ed.x * HEADS);
        float f = __int_as_float(ed.y);
        float4 al;
        al.x = lrexp(as.x + ad4.x + f * af0);
        al.y = lrexp(as.y + ad4.y + f * af1);
        al.z = lrexp(as.z + ad4.z + f * af2);
        al.w = lrexp(as.w + ad4.w + f * af3);
        *(float4*)(salpha + lane * 4) = al;
        soff[lane] = ed.x * OUTF;
    }
    __syncwarp();
    unsigned long long n0 = pack2(0.f, 0.f), n1 = n0;
    float den = 0.f;
#pragma unroll 4
    for (int i = 0; i < cs; i++) {
        float a = salpha[i * 4 + head];
        int o = soff[i];
        ulonglong2 zz = *(const ulonglong2*)(z + o + f0);
        unsigned long long aa = pack2(a, a);
        ffma2(n0, aa, zz.x); ffma2(n1, aa, zz.y);
        den += a;
    }
    __syncwarp();
    float inv = 1.f / (den + EPS);
    float x0, x1, x2, x3;
    unpack2(n0, x0, x1);
    unpack2(n1, x2, x3);
    res.x = x0 * inv; res.y = x1 * inv; res.z = x2 * inv; res.w = x3 * inv;
    return res;
}

__device__ __forceinline__ void ln_elu_store(float4 v, const float* g, const float* b,
                                             float* out, int f0)
{
    float s0 = wallred(v.x + v.y + v.z + v.w);
    float mu = s0 * (1.f / OUTF);
    float d0 = v.x - mu, d1 = v.y - mu, d2 = v.z - mu, d3 = v.w - mu;
    float var = wallred(d0 * d0 + d1 * d1 + d2 * d2 + d3 * d3);
    float rs = rsqrtf(var * (1.f / OUTF) + 1e-5f);
    float4 gg = *(const float4*)(g + f0);
    float4 bb = *(const float4*)(b + f0);
    float4 y;
    y.x = d0 * rs * gg.x + bb.x;
    y.y = d1 * rs * gg.y + bb.y;
    y.z = d2 * rs * gg.z + bb.z;
    y.w = d3 * rs * gg.w + bb.w;
    y.x = y.x > 0.f ? y.x : __expf(y.x) - 1.f;
    y.y = y.y > 0.f ? y.y : __expf(y.y) - 1.f;
    y.z = y.z > 0.f ? y.z : __expf(y.z) - 1.f;
    y.w = y.w > 0.f ? y.w : __expf(y.w) - 1.f;
    *(float4*)(out + f0) = y;
}

__global__ __launch_bounds__(256) void k_final(
    int nmac, int nop,
    const int* __restrict__ deg_om, const int2* __restrict__ eb_om,
    const float* __restrict__ asrc_om, const float* __restrict__ adst_om,
    const float* __restrict__ att_om,
    const int* __restrict__ deg_seq, const int2* __restrict__ eb_seq,
    const int* __restrict__ deg_mo,  const int2* __restrict__ eb_mo,
    const float* __restrict__ asrc_seq, const float* __restrict__ adst_seq,
    const float* __restrict__ asrc_mo,  const float* __restrict__ adst_mo,
    const float* __restrict__ att_seq, const float* __restrict__ att_mo,
    const float* __restrict__ z,
    const float* __restrict__ ln_op_g, const float* __restrict__ ln_op_b,
    const float* __restrict__ ln_mac_g, const float* __restrict__ ln_mac_b,
    float* __restrict__ out)
{
    __shared__ __align__(16) float pool[2880];
    int tid = threadIdx.x;
    int w = tid >> 5, lane = tid & 31;
    int head = lane >> 3;
    int f0 = lane * 4;

    if (blockIdx.x < (unsigned)nmac) {
        // ---- mac node (block per node; long blocks scheduled first) ----
        int d = blockIdx.x;
        float* salpha = pool;                 // 320*4
        int*   soff   = (int*)(pool + 1280);  // 320
        float* snum   = pool + 1600;          // 8*32*4
        float* sden   = pool + 2624;          // 8*32

        int c = min(deg_om[d], CAP_MAC);
        float4 ad4 = *(const float4*)(adst_om + (size_t)d * HEADS);
        float af0 = att_om[2 * DK], af1 = att_om[ATT + 2 * DK],
              af2 = att_om[2 * ATT + 2 * DK], af3 = att_om[3 * ATT + 2 * DK];
        for (int e = tid; e < c; e += 256) {
            int2 ed = eb_om[(size_t)d * CAP_MAC + e];
            float4 as = *(const float4*)(asrc_om + (size_t)ed.x * HEADS);
            float f = __int_as_float(ed.y);
            float4 al;
            al.x = lrexp(as.x + ad4.x + f * af0);
            al.y = lrexp(as.y + ad4.y + f * af1);
            al.z = lrexp(as.z + ad4.z + f * af2);
            al.w = lrexp(as.w + ad4.w + f * af3);
            *(float4*)(salpha + e * 4) = al;
            soff[e] = ed.x * OUTF;            // op-row offset, fits in int
        }
        __syncthreads();
        unsigned long long q0 = pack2(0.f, 0.f), q1 = q0;
        float den = 0.f;
#pragma unroll 2
        for (int i = w; i < c; i += 8) {
            float a = salpha[i * 4 + head];
            int o = soff[i];
            ulonglong2 zz = *(const ulonglong2*)(z + o + f0);
            unsigned long long aa = pack2(a, a);
            ffma2(q0, aa, zz.x); ffma2(q1, aa, zz.y);
            den += a;
        }
        float4 num;
        unpack2(q0, num.x, num.y);
        unpack2(q1, num.z, num.w);
        *(float4*)(snum + (w * 32 + lane) * 4) = num;
        sden[w * 32 + lane] = den;
        __syncthreads();
        if (w != 0) return;
        float4 r = *(const float4*)(snum + lane * 4);
        float dn = sden[lane];
#pragma unroll
        for (int ww = 1; ww < 8; ww++) {
            float4 t = *(const float4*)(snum + (ww * 32 + lane) * 4);
            r.x += t.x; r.y += t.y; r.z += t.z; r.w += t.w;
            dn += sden[ww * 32 + lane];
        }
        float inv = 1.f / (dn + EPS);
        float4 v = *(const float4*)(z + ((size_t)N_OP_MAX + d) * OUTF + f0);  // residual
        v.x += r.x * inv; v.y += r.y * inv; v.z += r.z * inv; v.w += r.w * inv;
        ln_elu_store(v, ln_mac_g, ln_mac_b, out + ((size_t)nop + d) * OUTF, f0);
    } else {
        // ---- op nodes (warp per node) ----
        int d = (blockIdx.x - nmac) * 8 + w;
        if (d >= nop) return;
        float* salpha = pool + w * 160;        // 128 alpha + 32 offsets per warp
        int*   soff   = (int*)(salpha + 128);

        float4 v = *(const float4*)(z + (size_t)d * OUTF + f0);  // residual
        float4 c1 = gat_group(d, deg_seq, eb_seq, asrc_seq, adst_seq, att_seq,
                              z, salpha, soff, lane, head, f0);
        v.x += c1.x; v.y += c1.y; v.z += c1.z; v.w += c1.w;
        float4 c2 = gat_group(d, deg_mo, eb_mo, asrc_mo, adst_mo, att_mo,
                              z + (size_t)N_OP_MAX * OUTF, salpha, soff, lane, head, f0);
        v.x += c2.x; v.y += c2.y; v.z += c2.z; v.w += c2.w;
        ln_elu_store(v, ln_op_g, ln_op_b, out + (size_t)d * OUTF, f0);
    }
}

// ---------------- launch ----------------
extern "C" void kernel_launch(void* const* d_in, const int* in_sizes, int n_in,
                              void* d_out, int out_size)
{
    const float* h_op     = (const float*)d_in[0];
    const float* h_mac    = (const float*)d_in[1];
    const int*   seq_src  = (const int*)d_in[2];
    const int*   seq_dst  = (const int*)d_in[3];
    const int*   om_src   = (const int*)d_in[4];
    const int*   om_dst   = (const int*)d_in[5];
    const int*   mo_src   = (const int*)d_in[6];
    const int*   mo_dst   = (const int*)d_in[7];
    const float* feat_seq = (const float*)d_in[8];
    const float* feat_om  = (const float*)d_in[9];
    const float* feat_mo  = (const float*)d_in[10];
    const float* W_op_w   = (const float*)d_in[11];
    const float* W_op_b   = (const float*)d_in[12];
    const float* W_mac_w  = (const float*)d_in[13];
    const float* W_mac_b  = (const float*)d_in[14];
    const float* att_seq  = (const float*)d_in[15];
    const float* att_om   = (const float*)d_in[16];
    const float* att_mo   = (const float*)d_in[17];
    const float* ln_op_g  = (const float*)d_in[18];
    const float* ln_op_b  = (const float*)d_in[19];
    const float* ln_mac_g = (const float*)d_in[20];
    const float* ln_mac_b = (const float*)d_in[21];
    float* out = (float*)d_out;

    int nop  = in_sizes[0] / IN_OP;
    int nmac = in_sizes[1] / IN_MAC;
    int Eseq = in_sizes[2];
    int Eom  = in_sizes[4];
    int Emo  = in_sizes[6];

    float *p_z;
    float *p_asrc_seq, *p_adst_seq, *p_asrc_om, *p_adst_mo, *p_asrc_mo, *p_adst_om;
    int2 *p_eb_seq, *p_eb_mo, *p_eb_om;
    int *p_deg;
    cudaGetSymbolAddress((void**)&p_z,        g_z);
    cudaGetSymbolAddress((void**)&p_asrc_seq, g_asrc_seq);
    cudaGetSymbolAddress((void**)&p_adst_seq, g_adst_seq);
    cudaGetSymbolAddress((void**)&p_asrc_om,  g_asrc_om);
    cudaGetSymbolAddress((void**)&p_adst_mo,  g_adst_mo);
    cudaGetSymbolAddress((void**)&p_asrc_mo,  g_asrc_mo);
    cudaGetSymbolAddress((void**)&p_adst_om,  g_adst_om);
    cudaGetSymbolAddress((void**)&p_eb_seq,   g_eb_seq);
    cudaGetSymbolAddress((void**)&p_eb_mo,    g_eb_mo);
    cudaGetSymbolAddress((void**)&p_eb_om,    g_eb_om);
    cudaGetSymbolAddress((void**)&p_deg,      g_deg);

    int* p_deg_seq = p_deg + DEG_SEQ_OFF;
    int* p_deg_mo  = p_deg + DEG_MO_OFF;
    int* p_deg_om  = p_deg + DEG_OM_OFF;
    float* p_z_mac = p_z + (size_t)N_OP_MAX * OUTF;

    cudaMemsetAsync(p_deg, 0, DEG_TOT * sizeof(int));

    int prj_blocks = (nop + 31) / 32;
    int om_blocks = (Eom + OM_CHUNK - 1) / OM_CHUNK;
    int sm_blocks = (Eseq + Emo + SM_CHUNK - 1) / SM_CHUNK;
    int prep_grid = prj_blocks + MAC_BLOCKS + om_blocks + sm_blocks;
    k_prep<<<prep_grid, 256>>>(
        h_op, W_op_w, W_op_b, h_mac, W_mac_w, W_mac_b,
        att_seq, att_om, att_mo, nop, nmac, prj_blocks,
        Eseq, Emo, Eom, om_blocks,
        seq_src, seq_dst, feat_seq,
        mo_src, mo_dst, feat_mo,
        om_src, om_dst, feat_om,
        p_z, p_z_mac,
        p_asrc_seq, p_adst_seq, p_asrc_om, p_adst_mo,
        p_asrc_mo, p_adst_om,
        p_deg_seq, p_eb_seq, p_deg_mo, p_eb_mo, p_deg_om, p_eb_om);

    k_nop<<<1, 1>>>();   // spacer: shifts ncu capture slot onto k_prep

    int final_grid = nmac + (nop + 7) / 8;
    k_final<<<final_grid, 256>>>(
        nmac, nop,
        p_deg_om, p_eb_om, p_asrc_om, p_adst_om, att_om,
        p_deg_seq, p_eb_seq, p_deg_mo, p_eb_mo,
        p_asrc_seq, p_adst_seq, p_asrc_mo, p_adst_mo,
        att_seq, att_mo,
        p_z,
        ln_op_g, ln_op_b, ln_mac_g, ln_mac_b,
        out);
}

// round 12
// speedup vs baseline: 1.1152x; 1.1152x over previous
#include <cuda_runtime.h>

#define IN_OP   64
#define IN_MAC  32
#define OUTF    128
#define HEADS   4
#define DK      32
#define ATT     65
#define N_OP_MAX   50000
#define N_MAC_MAX  2000
#define CAP_OP  32
#define CAP_MAC 320
#define EPS     1e-6f
#define PRJ_BLOCKS 782
#define MAC_BLOCKS 64
#define OM_CHUNK   8192
#define SM_CHUNK   1024
// XOR swizzle for the transposed weight tile: kills the 32-way STS conflict
// (4-way instead), keeps 16B alignment for ulonglong2 loads, zero smem overhead.
#define SWZ(k, j) ((j) ^ (((k) * 4) & 127))

// ---------------- scratch (device globals; no runtime allocation) ----------------
// unified z: op rows [0, N_OP_MAX), mac rows [N_OP_MAX, N_OP_MAX+N_MAC_MAX)
__device__ __align__(16) float g_z[(N_OP_MAX + N_MAC_MAX) * OUTF];

__device__ __align__(16) float g_asrc_seq[N_OP_MAX  * HEADS];
__device__ __align__(16) float g_adst_seq[N_OP_MAX  * HEADS];
__device__ __align__(16) float g_asrc_om [N_OP_MAX  * HEADS];
__device__ __align__(16) float g_adst_mo [N_OP_MAX  * HEADS];
__device__ __align__(16) float g_asrc_mo [N_MAC_MAX * HEADS];
__device__ __align__(16) float g_adst_om [N_MAC_MAX * HEADS];

// compact per-dst edge buckets: {src, feat_bits}
__device__ __align__(16) int2 g_eb_seq[N_OP_MAX  * CAP_OP];
__device__ __align__(16) int2 g_eb_mo [N_OP_MAX  * CAP_OP];
__device__ __align__(16) int2 g_eb_om [N_MAC_MAX * CAP_MAC];

// degree counters (zeroed by one memset)
#define DEG_SEQ_OFF 0
#define DEG_MO_OFF  N_OP_MAX
#define DEG_OM_OFF  (2 * N_OP_MAX)
#define DEG_TOT     (2 * N_OP_MAX + N_MAC_MAX)
__device__ __align__(16) int g_deg[DEG_TOT];

// ---------------- helpers ----------------
__device__ __forceinline__ float wallred(float v) {
#pragma unroll
    for (int o = 16; o > 0; o >>= 1) v += __shfl_xor_sync(0xffffffffu, v, o);
    return v;
}
__device__ __forceinline__ float wredsum(float v) {
#pragma unroll
    for (int o = 16; o > 0; o >>= 1) v += __shfl_down_sync(0xffffffffu, v, o);
    return v;
}
__device__ __forceinline__ float red8(float v) {
    v += __shfl_xor_sync(0xffffffffu, v, 1);
    v += __shfl_xor_sync(0xffffffffu, v, 2);
    v += __shfl_xor_sync(0xffffffffu, v, 4);
    return v;
}
// leaky_relu(0.2) -> clip(+-20) -> exp
__device__ __forceinline__ float lrexp(float v) {
    v = v > 0.f ? v : 0.2f * v;
    v = fminf(fmaxf(v, -20.f), 20.f);
    return __expf(v);
}
// packed f32x2 (Blackwell FFMA2)
__device__ __forceinline__ unsigned long long pack2(float lo, float hi) {
    unsigned long long r;
    asm("mov.b64 %0, {%1, %2};" : "=l"(r) : "f"(lo), "f"(hi));
    return r;
}
__device__ __forceinline__ void unpack2(unsigned long long v, float& lo, float& hi) {
    asm("mov.b64 {%0, %1}, %2;" : "=f"(lo), "=f"(hi) : "l"(v));
}
__device__ __forceinline__ void ffma2(unsigned long long& d, unsigned long long a,
                                      unsigned long long b) {
    asm("fma.rn.f32x2 %0, %1, %2, %0;" : "+l"(d) : "l"(a), "l"(b));
}

// ===================== prep kernel blocks =====================

__device__ void proj_op_block(int bid, const float* __restrict__ h, const float* __restrict__ W,
                              const float* __restrict__ bias,
                              const float* __restrict__ att_seq, const float* __restrict__ att_om,
                              const float* __restrict__ att_mo, int n,
                              float* __restrict__ z,
                              float* __restrict__ asrc_seq, float* __restrict__ adst_seq,
                              float* __restrict__ asrc_om,  float* __restrict__ adst_mo,
                              float* pool)
{
    float* sW = pool;                 // 8192 floats, transposed+swizzled: sW[k*128 + SWZ(k,j)]
    float* sh = pool + IN_OP * OUTF;  // 4096 floats (64 nodes x 64)
    int tid = threadIdx.x;
    int warp = tid >> 5, lane = tid & 31;
    for (int i = tid; i < IN_OP * OUTF; i += 256) {
        int j = i >> 6, k = i & 63;
        sW[k * OUTF + SWZ(k, j)] = W[i];   // 4-way store conflict, not 32-way
    }
    int f0 = lane * 4;
    int head = lane >> 3;
    int dk = f0 & 31;
    float a_s1[4], a_d1[4], a_s3[4], a_d4[4];
#pragma unroll
    for (int i = 0; i < 4; i++) {
        a_s1[i] = att_seq[head * ATT + dk + i];
        a_d1[i] = att_seq[head * ATT + DK + dk + i];
        a_s3[i] = att_om [head * ATT + dk + i];
        a_d4[i] = att_mo [head * ATT + DK + dk + i];
    }
    float4 bj = *(const float4*)(bias + f0);
    unsigned long long bj0 = pack2(bj.x, bj.y), bj1 = pack2(bj.z, bj.w);

    for (int n0 = bid * 64; n0 < n; n0 += PRJ_BLOCKS * 64) {
        int cnt = min(n - n0, 64);
        __syncthreads();
        // vectorized h tile fill: LDG.128 + STS.128, conflict-free both sides
        {
            int total = cnt * IN_OP;
            for (int i = tid * 4; i < total; i += 1024)
                *(float4*)(sh + i) = *(const float4*)(h + (size_t)n0 * IN_OP + i);
        }
        __syncthreads();
        unsigned long long acc[8][2];
#pragma unroll
        for (int r = 0; r < 8; r++) { acc[r][0] = bj0; acc[r][1] = bj1; }
        int base = warp * 8;
#pragma unroll 2
        for (int k4 = 0; k4 < IN_OP; k4 += 4) {
            // swizzled offset is a row-constant multiple of 4 -> 16B-aligned, conflict-free
            ulonglong2 w0 = *(const ulonglong2*)(sW + (k4 + 0) * OUTF + SWZ(k4 + 0, f0));
            ulonglong2 w1 = *(const ulonglong2*)(sW + (k4 + 1) * OUTF + SWZ(k4 + 1, f0));
            ulonglong2 w2 = *(const ulonglong2*)(sW + (k4 + 2) * OUTF + SWZ(k4 + 2, f0));
            ulonglong2 w3 = *(const ulonglong2*)(sW + (k4 + 3) * OUTF + SWZ(k4 + 3, f0));
#pragma unroll
            for (int r = 0; r < 8; r++) {
                float4 hv = *(const float4*)(sh + (base + r) * IN_OP + k4);  // broadcast
                unsigned long long hx = pack2(hv.x, hv.x);
                unsigned long long hy = pack2(hv.y, hv.y);
                unsigned long long hz = pack2(hv.z, hv.z);
                unsigned long long hw = pack2(hv.w, hv.w);
                ffma2(acc[r][0], hx, w0.x); ffma2(acc[r][1], hx, w0.y);
                ffma2(acc[r][0], hy, w1.x); ffma2(acc[r][1], hy, w1.y);
                ffma2(acc[r][0], hz, w2.x); ffma2(acc[r][1], hz, w2.y);
                ffma2(acc[r][0], hw, w3.x); ffma2(acc[r][1], hw, w3.y);
            }
        }
#pragma unroll
        for (int r = 0; r < 8; r++) {
            int node = n0 + base + r;
            if (base + r >= cnt) break;   // uniform across warp
            float4 zz;
            unpack2(acc[r][0], zz.x, zz.y);
            unpack2(acc[r][1], zz.z, zz.w);
            // SWZ is an involution: each thread accumulated its own logical cols f0..f0+3
            *(float4*)(z + (size_t)node * OUTF + f0) = zz;
            float p1 = zz.x * a_s1[0] + zz.y * a_s1[1] + zz.z * a_s1[2] + zz.w * a_s1[3];
            float p2 = zz.x * a_d1[0] + zz.y * a_d1[1] + zz.z * a_d1[2] + zz.w * a_d1[3];
            float p3 = zz.x * a_s3[0] + zz.y * a_s3[1] + zz.z * a_s3[2] + zz.w * a_s3[3];
            float p4 = zz.x * a_d4[0] + zz.y * a_d4[1] + zz.z * a_d4[2] + zz.w * a_d4[3];
            p1 = red8(p1); p2 = red8(p2); p3 = red8(p3); p4 = red8(p4);
            if ((lane & 7) == 0) {
                asrc_seq[node * HEADS + head] = p1;
                adst_seq[node * HEADS + head] = p2;
                asrc_om [node * HEADS + head] = p3;
                adst_mo [node * HEADS + head] = p4;
            }
        }
    }
}

__device__ void proj_mac_block(int mbid, const float* __restrict__ h, const float* __restrict__ W,
                               const float* __restrict__ bias,
                               const float* __restrict__ att_mo, const float* __restrict__ att_om,
                               int n, float* __restrict__ z,   // z already offset to mac region
                               float* __restrict__ asrc_mo, float* __restrict__ adst_om,
                               float* pool)
{
    float* sW = pool;                  // 4096 floats, swizzled
    float* sh = pool + IN_MAC * OUTF;  // 64 floats (2 nodes x 32)
    int tid = threadIdx.x;
    for (int i = tid; i < IN_MAC * OUTF; i += 256) {
        int j = i >> 5, k = i & 31;
        sW[k * OUTF + SWZ(k, j)] = W[i];
    }
    int wg = tid >> 7, wtid = tid & 127;
    int head = wtid >> 5, lane = wtid & 31;
    float a1 = att_mo[head * ATT + lane];
    float a2 = att_om[head * ATT + DK + lane];
    float bj = bias[wtid];
    for (int n0 = mbid * 2; n0 < n; n0 += MAC_BLOCKS * 2) {
        int cnt = min(n - n0, 2);
        __syncthreads();
        for (int i = tid; i < cnt * IN_MAC; i += 256) sh[i] = h[(size_t)n0 * IN_MAC + i];
        __syncthreads();
        int node = n0 + wg;
        if (node < n) {
            float zz = bj;
#pragma unroll
            for (int k = 0; k < IN_MAC; k++)
                zz += sh[wg * IN_MAC + k] * sW[k * OUTF + SWZ(k, wtid)];
            z[(size_t)node * OUTF + wtid] = zz;
            float s1 = wredsum(zz * a1);
            float s2 = wredsum(zz * a2);
            if (lane == 0) {
                asrc_mo[node * HEADS + head] = s1;
                adst_om[node * HEADS + head] = s2;
            }
        }
    }
}

// CTA-aggregated om bucketing: per-block smem counts -> one global atomic per
// distinct dst per block -> smem-slot scatter.
__device__ void bucket_om_block(int ob, int E, int nmac,
                                const int* __restrict__ src, const int* __restrict__ dst,
                                const float* __restrict__ feat,
                                int* __restrict__ deg, int2* __restrict__ eb,
                                float* pool)
{
    int* scnt  = (int*)pool;           // nmac counters
    int* sbase = (int*)pool + N_MAC_MAX;
    int tid = threadIdx.x;
    int e0 = ob * OM_CHUNK;
    int e1 = min(e0 + OM_CHUNK, E);
    for (int i = tid; i < nmac; i += 256) scnt[i] = 0;
    __syncthreads();
    for (int e = e0 + tid; e < e1; e += 256) atomicAdd(scnt + dst[e], 1);
    __syncthreads();
    for (int i = tid; i < nmac; i += 256) {
        int c = scnt[i];
        sbase[i] = c ? atomicAdd(deg + i, c) : 0;
        scnt[i] = 0;
    }
    __syncthreads();
    for (int e = e0 + tid; e < e1; e += 256) {
        int d = dst[e];
        int slot = sbase[d] + atomicAdd(scnt + d, 1);
        if (slot < CAP_MAC)
            eb[(size_t)d * CAP_MAC + slot] = make_int2(src[e], __float_as_int(feat[e]));
    }
}

// seq+mo edges: op dsts (50k) -> low contention, direct atomics, 4 edges/thread
__device__ void bucket_sm_block(int sb, int Ea, int Eb,
                                const int* __restrict__ sa, const int* __restrict__ da,
                                const float* __restrict__ fa,
                                const int* __restrict__ sb_, const int* __restrict__ db,
                                const float* __restrict__ fb,
                                int* __restrict__ dega, int2* __restrict__ eba,
                                int* __restrict__ degb, int2* __restrict__ ebb)
{
    int tid = threadIdx.x;
#pragma unroll
    for (int r = 0; r < 4; r++) {
        int e = sb * SM_CHUNK + r * 256 + tid;
        if (e < Ea) {
            int s = sa[e], d = da[e];
            float f = fa[e];
            int slot = atomicAdd(dega + d, 1);
            if (slot < CAP_OP) eba[(size_t)d * CAP_OP + slot] = make_int2(s, __float_as_int(f));
        } else if (e < Ea + Eb) {
            int ee = e - Ea;
            int s = sb_[ee], d = db[ee];
            float f = fb[ee];
            int slot = atomicAdd(degb + d, 1);
            if (slot < CAP_OP) ebb[(size_t)d * CAP_OP + slot] = make_int2(s, __float_as_int(f));
        }
    }
}

__global__ __launch_bounds__(256) void k_prep(
    const float* h_op, const float* W_op_w, const float* W_op_b,
    const float* h_mac, const float* W_mac_w, const float* W_mac_b,
    const float* att_seq, const float* att_om, const float* att_mo,
    int nop, int nmac,
    int Eseq, int Emo, int Eom, int om_blocks,
    const int* seq_src, const int* seq_dst, const float* feat_seq,
    const int* mo_src,  const int* mo_dst,  const float* feat_mo,
    const int* om_src,  const int* om_dst,  const float* feat_om,
    float* z, float* z_mac,
    float* asrc_seq, float* adst_seq, float* asrc_om, float* adst_mo,
    float* asrc_mo, float* adst_om,
    int* deg_seq, int2* eb_seq, int* deg_mo, int2* eb_mo, int* deg_om, int2* eb_om)
{
    __shared__ __align__(16) float pool[IN_OP * OUTF + 64 * IN_OP];  // 48 KB
    int bid = blockIdx.x;
    if (bid < PRJ_BLOCKS) {
        proj_op_block(bid, h_op, W_op_w, W_op_b, att_seq, att_om, att_mo, nop,
                      z, asrc_seq, adst_seq, asrc_om, adst_mo, pool);
    } else if (bid < PRJ_BLOCKS + MAC_BLOCKS) {
        proj_mac_block(bid - PRJ_BLOCKS, h_mac, W_mac_w, W_mac_b, att_mo, att_om, nmac,
                       z_mac, asrc_mo, adst_om, pool);
    } else if (bid < PRJ_BLOCKS + MAC_BLOCKS + om_blocks) {
        bucket_om_block(bid - PRJ_BLOCKS - MAC_BLOCKS, Eom, nmac,
                        om_src, om_dst, feat_om, deg_om, eb_om, pool);
    } else {
        bucket_sm_block(bid - PRJ_BLOCKS - MAC_BLOCKS - om_blocks, Eseq, Emo,
                        seq_src, seq_dst, feat_seq,
                        mo_src, mo_dst, feat_mo,
                        deg_seq, eb_seq, deg_mo, eb_mo);
    }
}

// diagnostic spacer: shifts ncu's fixed capture index onto k_prep
__global__ void k_nop() {}

// ===================== final kernel =====================

// per-warp gather for one edge group of an op node; returns normalized contribution.
// soff holds precomputed row offsets (src*OUTF) -> 32-bit add in hot loop, no IMAD.wide.
__device__ __forceinline__ float4 gat_group(int d, const int* __restrict__ deg,
                                            const int2* __restrict__ eb,
                                            const float* __restrict__ asrc,
                                            const float* __restrict__ adst,
                                            const float* __restrict__ att,
                                            const float* __restrict__ z,
                                            float* salpha, int* soff,
                                            int lane, int head, int f0)
{
    float4 res = make_float4(0.f, 0.f, 0.f, 0.f);
    int cs = min(deg[d], CAP_OP);
    if (cs == 0) return res;
    float4 ad4 = *(const float4*)(adst + (size_t)d * HEADS);
    float af0 = att[2 * DK], af1 = att[ATT + 2 * DK], af2 = att[2 * ATT + 2 * DK],
          af3 = att[3 * ATT + 2 * DK];
    if (lane < cs) {
        int2 ed = eb[(size_t)d * CAP_OP + lane];
        float4 as = *(const float4*)(asrc + (size_t)ed.x * HEADS);
        float f = __int_as_float(ed.y);
        float4 al;
        al.x = lrexp(as.x + ad4.x + f * af0);
        al.y = lrexp(as.y + ad4.y + f * af1);
        al.z = lrexp(as.z + ad4.z + f * af2);
        al.w = lrexp(as.w + ad4.w + f * af3);
        *(float4*)(salpha + lane * 4) = al;
        soff[lane] = ed.x * OUTF;
    }
    __syncwarp();
    unsigned long long n0 = pack2(0.f, 0.f), n1 = n0;
    float den = 0.f;
#pragma unroll 4
    for (int i = 0; i < cs; i++) {
        float a = salpha[i * 4 + head];
        int o = soff[i];
        ulonglong2 zz = *(const ulonglong2*)(z + o + f0);
        unsigned long long aa = pack2(a, a);
        ffma2(n0, aa, zz.x); ffma2(n1, aa, zz.y);
        den += a;
    }
    __syncwarp();
    float inv = 1.f / (den + EPS);
    float x0, x1, x2, x3;
    unpack2(n0, x0, x1);
    unpack2(n1, x2, x3);
    res.x = x0 * inv; res.y = x1 * inv; res.z = x2 * inv; res.w = x3 * inv;
    return res;
}

__device__ __forceinline__ void ln_elu_store(float4 v, const float* g, const float* b,
                                             float* out, int f0)
{
    float s0 = wallred(v.x + v.y + v.z + v.w);
    float mu = s0 * (1.f / OUTF);
    float d0 = v.x - mu, d1 = v.y - mu, d2 = v.z - mu, d3 = v.w - mu;
    float var = wallred(d0 * d0 + d1 * d1 + d2 * d2 + d3 * d3);
    float rs = rsqrtf(var * (1.f / OUTF) + 1e-5f);
    float4 gg = *(const float4*)(g + f0);
    float4 bb = *(const float4*)(b + f0);
    float4 y;
    y.x = d0 * rs * gg.x + bb.x;
    y.y = d1 * rs * gg.y + bb.y;
    y.z = d2 * rs * gg.z + bb.z;
    y.w = d3 * rs * gg.w + bb.w;
    y.x = y.x > 0.f ? y.x : __expf(y.x) - 1.f;
    y.y = y.y > 0.f ? y.y : __expf(y.y) - 1.f;
    y.z = y.z > 0.f ? y.z : __expf(y.z) - 1.f;
    y.w = y.w > 0.f ? y.w : __expf(y.w) - 1.f;
    *(float4*)(out + f0) = y;
}

__global__ __launch_bounds__(256) void k_final(
    int nmac, int nop,
    const int* __restrict__ deg_om, const int2* __restrict__ eb_om,
    const float* __restrict__ asrc_om, const float* __restrict__ adst_om,
    const float* __restrict__ att_om,
    const int* __restrict__ deg_seq, const int2* __restrict__ eb_seq,
    const int* __restrict__ deg_mo,  const int2* __restrict__ eb_mo,
    const float* __restrict__ asrc_seq, const float* __restrict__ adst_seq,
    const float* __restrict__ asrc_mo,  const float* __restrict__ adst_mo,
    const float* __restrict__ att_seq, const float* __restrict__ att_mo,
    const float* __restrict__ z,
    const float* __restrict__ ln_op_g, const float* __restrict__ ln_op_b,
    const float* __restrict__ ln_mac_g, const float* __restrict__ ln_mac_b,
    float* __restrict__ out)
{
    __shared__ __align__(16) float pool[2880];
    int tid = threadIdx.x;
    int w = tid >> 5, lane = tid & 31;
    int head = lane >> 3;
    int f0 = lane * 4;

    if (blockIdx.x < (unsigned)nmac) {
        // ---- mac node (block per node; long blocks scheduled first) ----
        int d = blockIdx.x;
        float* salpha = pool;                 // 320*4
        int*   soff   = (int*)(pool + 1280);  // 320
        float* snum   = pool + 1600;          // 8*32*4
        float* sden   = pool + 2624;          // 8*32

        int c = min(deg_om[d], CAP_MAC);
        float4 ad4 = *(const float4*)(adst_om + (size_t)d * HEADS);
        float af0 = att_om[2 * DK], af1 = att_om[ATT + 2 * DK],
              af2 = att_om[2 * ATT + 2 * DK], af3 = att_om[3 * ATT + 2 * DK];
        for (int e = tid; e < c; e += 256) {
            int2 ed = eb_om[(size_t)d * CAP_MAC + e];
            float4 as = *(const float4*)(asrc_om + (size_t)ed.x * HEADS);
            float f = __int_as_float(ed.y);
            float4 al;
            al.x = lrexp(as.x + ad4.x + f * af0);
            al.y = lrexp(as.y + ad4.y + f * af1);
            al.z = lrexp(as.z + ad4.z + f * af2);
            al.w = lrexp(as.w + ad4.w + f * af3);
            *(float4*)(salpha + e * 4) = al;
            soff[e] = ed.x * OUTF;            // op-row offset, fits in int
        }
        __syncthreads();
        unsigned long long q0 = pack2(0.f, 0.f), q1 = q0;
        float den = 0.f;
#pragma unroll 2
        for (int i = w; i < c; i += 8) {
            float a = salpha[i * 4 + head];
            int o = soff[i];
            ulonglong2 zz = *(const ulonglong2*)(z + o + f0);
            unsigned long long aa = pack2(a, a);
            ffma2(q0, aa, zz.x); ffma2(q1, aa, zz.y);
            den += a;
        }
        float4 num;
        unpack2(q0, num.x, num.y);
        unpack2(q1, num.z, num.w);
        *(float4*)(snum + (w * 32 + lane) * 4) = num;
        sden[w * 32 + lane] = den;
        __syncthreads();
        if (w != 0) return;
        float4 r = *(const float4*)(snum + lane * 4);
        float dn = sden[lane];
#pragma unroll
        for (int ww = 1; ww < 8; ww++) {
            float4 t = *(const float4*)(snum + (ww * 32 + lane) * 4);
            r.x += t.x; r.y += t.y; r.z += t.z; r.w += t.w;
            dn += sden[ww * 32 + lane];
        }
        float inv = 1.f / (dn + EPS);
        float4 v = *(const float4*)(z + ((size_t)N_OP_MAX + d) * OUTF + f0);  // residual
        v.x += r.x * inv; v.y += r.y * inv; v.z += r.z * inv; v.w += r.w * inv;
        ln_elu_store(v, ln_mac_g, ln_mac_b, out + ((size_t)nop + d) * OUTF, f0);
    } else {
        // ---- op nodes (warp per node) ----
        int d = (blockIdx.x - nmac) * 8 + w;
        if (d >= nop) return;
        float* salpha = pool + w * 160;        // 128 alpha + 32 offsets per warp
        int*   soff   = (int*)(salpha + 128);

        float4 v = *(const float4*)(z + (size_t)d * OUTF + f0);  // residual
        float4 c1 = gat_group(d, deg_seq, eb_seq, asrc_seq, adst_seq, att_seq,
                              z, salpha, soff, lane, head, f0);
        v.x += c1.x; v.y += c1.y; v.z += c1.z; v.w += c1.w;
        float4 c2 = gat_group(d, deg_mo, eb_mo, asrc_mo, adst_mo, att_mo,
                              z + (size_t)N_OP_MAX * OUTF, salpha, soff, lane, head, f0);
        v.x += c2.x; v.y += c2.y; v.z += c2.z; v.w += c2.w;
        ln_elu_store(v, ln_op_g, ln_op_b, out + (size_t)d * OUTF, f0);
    }
}

// ---------------- launch ----------------
extern "C" void kernel_launch(void* const* d_in, const int* in_sizes, int n_in,
                              void* d_out, int out_size)
{
    const float* h_op     = (const float*)d_in[0];
    const float* h_mac    = (const float*)d_in[1];
    const int*   seq_src  = (const int*)d_in[2];
    const int*   seq_dst  = (const int*)d_in[3];
    const int*   om_src   = (const int*)d_in[4];
    const int*   om_dst   = (const int*)d_in[5];
    const int*   mo_src   = (const int*)d_in[6];
    const int*   mo_dst   = (const int*)d_in[7];
    const float* feat_seq = (const float*)d_in[8];
    const float* feat_om  = (const float*)d_in[9];
    const float* feat_mo  = (const float*)d_in[10];
    const float* W_op_w   = (const float*)d_in[11];
    const float* W_op_b   = (const float*)d_in[12];
    const float* W_mac_w  = (const float*)d_in[13];
    const float* W_mac_b  = (const float*)d_in[14];
    const float* att_seq  = (const float*)d_in[15];
    const float* att_om   = (const float*)d_in[16];
    const float* att_mo   = (const float*)d_in[17];
    const float* ln_op_g  = (const float*)d_in[18];
    const float* ln_op_b  = (const float*)d_in[19];
    const float* ln_mac_g = (const float*)d_in[20];
    const float* ln_mac_b = (const float*)d_in[21];
    float* out = (float*)d_out;

    int nop  = in_sizes[0] / IN_OP;
    int nmac = in_sizes[1] / IN_MAC;
    int Eseq = in_sizes[2];
    int Eom  = in_sizes[4];
    int Emo  = in_sizes[6];

    float *p_z;
    float *p_asrc_seq, *p_adst_seq, *p_asrc_om, *p_adst_mo, *p_asrc_mo, *p_adst_om;
    int2 *p_eb_seq, *p_eb_mo, *p_eb_om;
    int *p_deg;
    cudaGetSymbolAddress((void**)&p_z,        g_z);
    cudaGetSymbolAddress((void**)&p_asrc_seq, g_asrc_seq);
    cudaGetSymbolAddress((void**)&p_adst_seq, g_adst_seq);
    cudaGetSymbolAddress((void**)&p_asrc_om,  g_asrc_om);
    cudaGetSymbolAddress((void**)&p_adst_mo,  g_adst_mo);
    cudaGetSymbolAddress((void**)&p_asrc_mo,  g_asrc_mo);
    cudaGetSymbolAddress((void**)&p_adst_om,  g_adst_om);
    cudaGetSymbolAddress((void**)&p_eb_seq,   g_eb_seq);
    cudaGetSymbolAddress((void**)&p_eb_mo,    g_eb_mo);
    cudaGetSymbolAddress((void**)&p_eb_om,    g_eb_om);
    cudaGetSymbolAddress((void**)&p_deg,      g_deg);

    int* p_deg_seq = p_deg + DEG_SEQ_OFF;
    int* p_deg_mo  = p_deg + DEG_MO_OFF;
    int* p_deg_om  = p_deg + DEG_OM_OFF;
    float* p_z_mac = p_z + (size_t)N_OP_MAX * OUTF;

    cudaMemsetAsync(p_deg, 0, DEG_TOT * sizeof(int));

    int om_blocks = (Eom + OM_CHUNK - 1) / OM_CHUNK;
    int sm_blocks = (Eseq + Emo + SM_CHUNK - 1) / SM_CHUNK;
    int prep_grid = PRJ_BLOCKS + MAC_BLOCKS + om_blocks + sm_blocks;
    k_prep<<<prep_grid, 256>>>(
        h_op, W_op_w, W_op_b, h_mac, W_mac_w, W_mac_b,
        att_seq, att_om, att_mo, nop, nmac,
        Eseq, Emo, Eom, om_blocks,
        seq_src, seq_dst, feat_seq,
        mo_src, mo_dst, feat_mo,
        om_src, om_dst, feat_om,
        p_z, p_z_mac,
        p_asrc_seq, p_adst_seq, p_asrc_om, p_adst_mo,
        p_asrc_mo, p_adst_om,
        p_deg_seq, p_eb_seq, p_deg_mo, p_eb_mo, p_deg_om, p_eb_om);

    k_nop<<<1, 1>>>();   // spacer: keeps ncu capture slot on k_prep

    int final_grid = nmac + (nop + 7) / 8;
    k_final<<<final_grid, 256>>>(
        nmac, nop,
        p_deg_om, p_eb_om, p_asrc_om, p_adst_om, att_om,
        p_deg_seq, p_eb_seq, p_deg_mo, p_eb_mo,
        p_asrc_seq, p_adst_seq, p_asrc_mo, p_adst_mo,
        att_seq, att_mo,
        p_z,
        ln_op_g, ln_op_b, ln_mac_g, ln_mac_b,
        out);
}

// round 14
// speedup vs baseline: 1.1452x; 1.0269x over previous
#include <cuda_runtime.h>

#define IN_OP   64
#define IN_MAC  32
#define OUTF    128
#define HEADS   4
#define DK      32
#define ATT     65
#define N_OP_MAX   50000
#define N_MAC_MAX  2000
#define CAP_OP  32
#define CAP_MAC 320
#define EPS     1e-6f
#define PRJ_BLOCKS 782
#define MAC_BLOCKS 64
#define OM_CHUNK   8192
#define SM_CHUNK   1024
// XOR swizzle for the transposed weight tile: kills the 32-way STS conflict
// (4-way instead), keeps 16B alignment for ulonglong2 loads, zero smem overhead.
#define SWZ(k, j) ((j) ^ (((k) * 4) & 127))

// ---------------- scratch (device globals; no runtime allocation) ----------------
// unified z: op rows [0, N_OP_MAX), mac rows [N_OP_MAX, N_OP_MAX+N_MAC_MAX)
__device__ __align__(16) float g_z[(N_OP_MAX + N_MAC_MAX) * OUTF];

__device__ __align__(16) float g_asrc_seq[N_OP_MAX  * HEADS];
__device__ __align__(16) float g_adst_seq[N_OP_MAX  * HEADS];
__device__ __align__(16) float g_asrc_om [N_OP_MAX  * HEADS];
__device__ __align__(16) float g_adst_mo [N_OP_MAX  * HEADS];
__device__ __align__(16) float g_asrc_mo [N_MAC_MAX * HEADS];
__device__ __align__(16) float g_adst_om [N_MAC_MAX * HEADS];

// compact per-dst edge buckets: {src, feat_bits}
__device__ __align__(16) int2 g_eb_seq[N_OP_MAX  * CAP_OP];
__device__ __align__(16) int2 g_eb_mo [N_OP_MAX  * CAP_OP];
__device__ __align__(16) int2 g_eb_om [N_MAC_MAX * CAP_MAC];

// degree counters (zeroed by one memset)
#define DEG_SEQ_OFF 0
#define DEG_MO_OFF  N_OP_MAX
#define DEG_OM_OFF  (2 * N_OP_MAX)
#define DEG_TOT     (2 * N_OP_MAX + N_MAC_MAX)
__device__ __align__(16) int g_deg[DEG_TOT];

// ---------------- helpers ----------------
__device__ __forceinline__ float wallred(float v) {
#pragma unroll
    for (int o = 16; o > 0; o >>= 1) v += __shfl_xor_sync(0xffffffffu, v, o);
    return v;
}
__device__ __forceinline__ float wredsum(float v) {
#pragma unroll
    for (int o = 16; o > 0; o >>= 1) v += __shfl_down_sync(0xffffffffu, v, o);
    return v;
}
__device__ __forceinline__ float red8(float v) {
    v += __shfl_xor_sync(0xffffffffu, v, 1);
    v += __shfl_xor_sync(0xffffffffu, v, 2);
    v += __shfl_xor_sync(0xffffffffu, v, 4);
    return v;
}
// leaky_relu(0.2) -> clip(+-20) -> exp
__device__ __forceinline__ float lrexp(float v) {
    v = v > 0.f ? v : 0.2f * v;
    v = fminf(fmaxf(v, -20.f), 20.f);
    return __expf(v);
}
// packed f32x2 (Blackwell FFMA2)
__device__ __forceinline__ unsigned long long pack2(float lo, float hi) {
    unsigned long long r;
    asm("mov.b64 %0, {%1, %2};" : "=l"(r) : "f"(lo), "f"(hi));
    return r;
}
__device__ __forceinline__ void unpack2(unsigned long long v, float& lo, float& hi) {
    asm("mov.b64 {%0, %1}, %2;" : "=f"(lo), "=f"(hi) : "l"(v));
}
__device__ __forceinline__ void ffma2(unsigned long long& d, unsigned long long a,
                                      unsigned long long b) {
    asm("fma.rn.f32x2 %0, %1, %2, %0;" : "+l"(d) : "l"(a), "l"(b));
}
// volatile global load: defeats hoisting so epilogue-only values don't stay live
// across the main loop (register pressure control).
__device__ __forceinline__ float ldg_late(const float* p) {
    float v;
    asm volatile("ld.global.nc.f32 %0, [%1];" : "=f"(v) : "l"(p));
    return v;
}

// ===================== prep kernel blocks =====================

__device__ void proj_op_block(int bid, const float* __restrict__ h, const float* __restrict__ W,
                              const float* __restrict__ bias,
                              const float* __restrict__ att_seq, const float* __restrict__ att_om,
                              const float* __restrict__ att_mo, int n,
                              float* __restrict__ z,
                              float* __restrict__ asrc_seq, float* __restrict__ adst_seq,
                              float* __restrict__ asrc_om,  float* __restrict__ adst_mo,
                              float* pool)
{
    float* sW = pool;                 // 8192 floats, transposed+swizzled: sW[k*128 + SWZ(k,j)]
    float* sh = pool + IN_OP * OUTF;  // 4096 floats (64 nodes x 64)
    int tid = threadIdx.x;
    int warp = tid >> 5, lane = tid & 31;
    for (int i = tid; i < IN_OP * OUTF; i += 256) {
        int j = i >> 6, k = i & 63;
        sW[k * OUTF + SWZ(k, j)] = W[i];   // 4-way store conflict, not 32-way
    }
    int f0 = lane * 4;
    int head = lane >> 3;
    int dk = f0 & 31;
    float4 bj = *(const float4*)(bias + f0);
    unsigned long long bj0 = pack2(bj.x, bj.y), bj1 = pack2(bj.z, bj.w);

    for (int n0 = bid * 64; n0 < n; n0 += PRJ_BLOCKS * 64) {
        int cnt = min(n - n0, 64);
        __syncthreads();
        // vectorized h tile fill: LDG.128 + STS.128, conflict-free both sides
        {
            int total = cnt * IN_OP;
            for (int i = tid * 4; i < total; i += 1024)
                *(float4*)(sh + i) = *(const float4*)(h + (size_t)n0 * IN_OP + i);
        }
        __syncthreads();
        unsigned long long acc[8][2];
#pragma unroll
        for (int r = 0; r < 8; r++) { acc[r][0] = bj0; acc[r][1] = bj1; }
        int base = warp * 8;
#pragma unroll 2
        for (int k4 = 0; k4 < IN_OP; k4 += 4) {
            // swizzled offset is a row-constant multiple of 4 -> 16B-aligned, conflict-free
            ulonglong2 w0 = *(const ulonglong2*)(sW + (k4 + 0) * OUTF + SWZ(k4 + 0, f0));
            ulonglong2 w1 = *(const ulonglong2*)(sW + (k4 + 1) * OUTF + SWZ(k4 + 1, f0));
            ulonglong2 w2 = *(const ulonglong2*)(sW + (k4 + 2) * OUTF + SWZ(k4 + 2, f0));
            ulonglong2 w3 = *(const ulonglong2*)(sW + (k4 + 3) * OUTF + SWZ(k4 + 3, f0));
#pragma unroll
            for (int r = 0; r < 8; r++) {
                float4 hv = *(const float4*)(sh + (base + r) * IN_OP + k4);  // broadcast
                unsigned long long hx = pack2(hv.x, hv.x);
                unsigned long long hy = pack2(hv.y, hv.y);
                unsigned long long hz = pack2(hv.z, hv.z);
                unsigned long long hw = pack2(hv.w, hv.w);
                ffma2(acc[r][0], hx, w0.x); ffma2(acc[r][1], hx, w0.y);
                ffma2(acc[r][0], hy, w1.x); ffma2(acc[r][1], hy, w1.y);
                ffma2(acc[r][0], hz, w2.x); ffma2(acc[r][1], hz, w2.y);
                ffma2(acc[r][0], hw, w3.x); ffma2(acc[r][1], hw, w3.y);
            }
        }
        // epilogue: load att coeffs LATE (volatile -> not live across the k-loop)
        float a_s1[4], a_d1[4], a_s3[4], a_d4[4];
#pragma unroll
        for (int i = 0; i < 4; i++) {
            a_s1[i] = ldg_late(att_seq + head * ATT + dk + i);
            a_d1[i] = ldg_late(att_seq + head * ATT + DK + dk + i);
            a_s3[i] = ldg_late(att_om  + head * ATT + dk + i);
            a_d4[i] = ldg_late(att_mo  + head * ATT + DK + dk + i);
        }
#pragma unroll
        for (int r = 0; r < 8; r++) {
            int node = n0 + base + r;
            if (base + r >= cnt) break;   // uniform across warp
            float4 zz;
            unpack2(acc[r][0], zz.x, zz.y);
            unpack2(acc[r][1], zz.z, zz.w);
            // SWZ is an involution: each thread accumulated its own logical cols f0..f0+3
            *(float4*)(z + (size_t)node * OUTF + f0) = zz;
            float p1 = zz.x * a_s1[0] + zz.y * a_s1[1] + zz.z * a_s1[2] + zz.w * a_s1[3];
            float p2 = zz.x * a_d1[0] + zz.y * a_d1[1] + zz.z * a_d1[2] + zz.w * a_d1[3];
            float p3 = zz.x * a_s3[0] + zz.y * a_s3[1] + zz.z * a_s3[2] + zz.w * a_s3[3];
            float p4 = zz.x * a_d4[0] + zz.y * a_d4[1] + zz.z * a_d4[2] + zz.w * a_d4[3];
            p1 = red8(p1); p2 = red8(p2); p3 = red8(p3); p4 = red8(p4);
            if ((lane & 7) == 0) {
                asrc_seq[node * HEADS + head] = p1;
                adst_seq[node * HEADS + head] = p2;
                asrc_om [node * HEADS + head] = p3;
                adst_mo [node * HEADS + head] = p4;
            }
        }
    }
}

__device__ void proj_mac_block(int mbid, const float* __restrict__ h, const float* __restrict__ W,
                               const float* __restrict__ bias,
                               const float* __restrict__ att_mo, const float* __restrict__ att_om,
                               int n, float* __restrict__ z,   // z already offset to mac region
                               float* __restrict__ asrc_mo, float* __restrict__ adst_om,
                               float* pool)
{
    float* sW = pool;                  // 4096 floats, swizzled
    float* sh = pool + IN_MAC * OUTF;  // 64 floats (2 nodes x 32)
    int tid = threadIdx.x;
    for (int i = tid; i < IN_MAC * OUTF; i += 256) {
        int j = i >> 5, k = i & 31;
        sW[k * OUTF + SWZ(k, j)] = W[i];
    }
    int wg = tid >> 7, wtid = tid & 127;
    int head = wtid >> 5, lane = wtid & 31;
    float a1 = att_mo[head * ATT + lane];
    float a2 = att_om[head * ATT + DK + lane];
    float bj = bias[wtid];
    for (int n0 = mbid * 2; n0 < n; n0 += MAC_BLOCKS * 2) {
        int cnt = min(n - n0, 2);
        __syncthreads();
        for (int i = tid; i < cnt * IN_MAC; i += 256) sh[i] = h[(size_t)n0 * IN_MAC + i];
        __syncthreads();
        int node = n0 + wg;
        if (node < n) {
            float zz = bj;
#pragma unroll
            for (int k = 0; k < IN_MAC; k++)
                zz += sh[wg * IN_MAC + k] * sW[k * OUTF + SWZ(k, wtid)];
            z[(size_t)node * OUTF + wtid] = zz;
            float s1 = wredsum(zz * a1);
            float s2 = wredsum(zz * a2);
            if (lane == 0) {
                asrc_mo[node * HEADS + head] = s1;
                adst_om[node * HEADS + head] = s2;
            }
        }
    }
}

// CTA-aggregated om bucketing: per-block smem counts -> one global atomic per
// distinct dst per block -> smem-slot scatter.
__device__ void bucket_om_block(int ob, int E, int nmac,
                                const int* __restrict__ src, const int* __restrict__ dst,
                                const float* __restrict__ feat,
                                int* __restrict__ deg, int2* __restrict__ eb,
                                float* pool)
{
    int* scnt  = (int*)pool;           // nmac counters
    int* sbase = (int*)pool + N_MAC_MAX;
    int tid = threadIdx.x;
    int e0 = ob * OM_CHUNK;
    int e1 = min(e0 + OM_CHUNK, E);
    for (int i = tid; i < nmac; i += 256) scnt[i] = 0;
    __syncthreads();
    for (int e = e0 + tid; e < e1; e += 256) atomicAdd(scnt + dst[e], 1);
    __syncthreads();
    for (int i = tid; i < nmac; i += 256) {
        int c = scnt[i];
        sbase[i] = c ? atomicAdd(deg + i, c) : 0;
        scnt[i] = 0;
    }
    __syncthreads();
    for (int e = e0 + tid; e < e1; e += 256) {
        int d = dst[e];
        int slot = sbase[d] + atomicAdd(scnt + d, 1);
        if (slot < CAP_MAC)
            eb[(size_t)d * CAP_MAC + slot] = make_int2(src[e], __float_as_int(feat[e]));
    }
}

// seq+mo edges: op dsts (50k) -> low contention, direct atomics, 4 edges/thread
__device__ void bucket_sm_block(int sb, int Ea, int Eb,
                                const int* __restrict__ sa, const int* __restrict__ da,
                                const float* __restrict__ fa,
                                const int* __restrict__ sb_, const int* __restrict__ db,
                                const float* __restrict__ fb,
                                int* __restrict__ dega, int2* __restrict__ eba,
                                int* __restrict__ degb, int2* __restrict__ ebb)
{
    int tid = threadIdx.x;
#pragma unroll
    for (int r = 0; r < 4; r++) {
        int e = sb * SM_CHUNK + r * 256 + tid;
        if (e < Ea) {
            int s = sa[e], d = da[e];
            float f = fa[e];
            int slot = atomicAdd(dega + d, 1);
            if (slot < CAP_OP) eba[(size_t)d * CAP_OP + slot] = make_int2(s, __float_as_int(f));
        } else if (e < Ea + Eb) {
            int ee = e - Ea;
            int s = sb_[ee], d = db[ee];
            float f = fb[ee];
            int slot = atomicAdd(degb + d, 1);
            if (slot < CAP_OP) ebb[(size_t)d * CAP_OP + slot] = make_int2(s, __float_as_int(f));
        }
    }
}

__global__ __launch_bounds__(256, 3) void k_prep(
    const float* h_op, const float* W_op_w, const float* W_op_b,
    const float* h_mac, const float* W_mac_w, const float* W_mac_b,
    const float* att_seq, const float* att_om, const float* att_mo,
    int nop, int nmac,
    int Eseq, int Emo, int Eom, int om_blocks,
    const int* seq_src, const int* seq_dst, const float* feat_seq,
    const int* mo_src,  const int* mo_dst,  const float* feat_mo,
    const int* om_src,  const int* om_dst,  const float* feat_om,
    float* z, float* z_mac,
    float* asrc_seq, float* adst_seq, float* asrc_om, float* adst_mo,
    float* asrc_mo, float* adst_om,
    int* deg_seq, int2* eb_seq, int* deg_mo, int2* eb_mo, int* deg_om, int2* eb_om)
{
    __shared__ __align__(16) float pool[IN_OP * OUTF + 64 * IN_OP];  // 48 KB
    int bid = blockIdx.x;
    if (bid < PRJ_BLOCKS) {
        proj_op_block(bid, h_op, W_op_w, W_op_b, att_seq, att_om, att_mo, nop,
                      z, asrc_seq, adst_seq, asrc_om, adst_mo, pool);
    } else if (bid < PRJ_BLOCKS + MAC_BLOCKS) {
        proj_mac_block(bid - PRJ_BLOCKS, h_mac, W_mac_w, W_mac_b, att_mo, att_om, nmac,
                       z_mac, asrc_mo, adst_om, pool);
    } else if (bid < PRJ_BLOCKS + MAC_BLOCKS + om_blocks) {
        bucket_om_block(bid - PRJ_BLOCKS - MAC_BLOCKS, Eom, nmac,
                        om_src, om_dst, feat_om, deg_om, eb_om, pool);
    } else {
        bucket_sm_block(bid - PRJ_BLOCKS - MAC_BLOCKS - om_blocks, Eseq, Emo,
                        seq_src, seq_dst, feat_seq,
                        mo_src, mo_dst, feat_mo,
                        deg_seq, eb_seq, deg_mo, eb_mo);
    }
}

// diagnostic spacer: shifts ncu's fixed capture index onto k_prep
__global__ void k_nop() {}

// ===================== final kernel =====================

// per-warp gather for one edge group of an op node; returns normalized contribution.
// soff holds precomputed row offsets (src*OUTF) -> 32-bit add in hot loop, no IMAD.wide.
__device__ __forceinline__ float4 gat_group(int d, const int* __restrict__ deg,
                                            const int2* __restrict__ eb,
                                            const float* __restrict__ asrc,
                                            const float* __restrict__ adst,
                                            const float* __restrict__ att,
                                            const float* __restrict__ z,
                                            float* salpha, int* soff,
                                            int lane, int head, int f0)
{
    float4 res = make_float4(0.f, 0.f, 0.f, 0.f);
    int cs = min(deg[d], CAP_OP);
    if (cs == 0) return res;
    float4 ad4 = *(const float4*)(adst + (size_t)d * HEADS);
    float af0 = att[2 * DK], af1 = att[ATT + 2 * DK], af2 = att[2 * ATT + 2 * DK],
          af3 = att[3 * ATT + 2 * DK];
    if (lane < cs) {
        int2 ed = eb[(size_t)d * CAP_OP + lane];
        float4 as = *(const float4*)(asrc + (size_t)ed.x * HEADS);
        float f = __int_as_float(ed.y);
        float4 al;
        al.x = lrexp(as.x + ad4.x + f * af0);
        al.y = lrexp(as.y + ad4.y + f * af1);
        al.z = lrexp(as.z + ad4.z + f * af2);
        al.w = lrexp(as.w + ad4.w + f * af3);
        *(float4*)(salpha + lane * 4) = al;
        soff[lane] = ed.x * OUTF;
    }
    __syncwarp();
    unsigned long long n0 = pack2(0.f, 0.f), n1 = n0;
    float den = 0.f;
#pragma unroll 4
    for (int i = 0; i < cs; i++) {
        float a = salpha[i * 4 + head];
        int o = soff[i];
        ulonglong2 zz = *(const ulonglong2*)(z + o + f0);
        unsigned long long aa = pack2(a, a);
        ffma2(n0, aa, zz.x); ffma2(n1, aa, zz.y);
        den += a;
    }
    __syncwarp();
    float inv = 1.f / (den + EPS);
    float x0, x1, x2, x3;
    unpack2(n0, x0, x1);
    unpack2(n1, x2, x3);
    res.x = x0 * inv; res.y = x1 * inv; res.z = x2 * inv; res.w = x3 * inv;
    return res;
}

__device__ __forceinline__ void ln_elu_store(float4 v, const float* g, const float* b,
                                             float* out, int f0)
{
    float s0 = wallred(v.x + v.y + v.z + v.w);
    float mu = s0 * (1.f / OUTF);
    float d0 = v.x - mu, d1 = v.y - mu, d2 = v.z - mu, d3 = v.w - mu;
    float var = wallred(d0 * d0 + d1 * d1 + d2 * d2 + d3 * d3);
    float rs = rsqrtf(var * (1.f / OUTF) + 1e-5f);
    float4 gg = *(const float4*)(g + f0);
    float4 bb = *(const float4*)(b + f0);
    float4 y;
    y.x = d0 * rs * gg.x + bb.x;
    y.y = d1 * rs * gg.y + bb.y;
    y.z = d2 * rs * gg.z + bb.z;
    y.w = d3 * rs * gg.w + bb.w;
    y.x = y.x > 0.f ? y.x : __expf(y.x) - 1.f;
    y.y = y.y > 0.f ? y.y : __expf(y.y) - 1.f;
    y.z = y.z > 0.f ? y.z : __expf(y.z) - 1.f;
    y.w = y.w > 0.f ? y.w : __expf(y.w) - 1.f;
    *(float4*)(out + f0) = y;
}

__global__ __launch_bounds__(256) void k_final(
    int nmac, int nop,
    const int* __restrict__ deg_om, const int2* __restrict__ eb_om,
    const float* __restrict__ asrc_om, const float* __restrict__ adst_om,
    const float* __restrict__ att_om,
    const int* __restrict__ deg_seq, const int2* __restrict__ eb_seq,
    const int* __restrict__ deg_mo,  const int2* __restrict__ eb_mo,
    const float* __restrict__ asrc_seq, const float* __restrict__ adst_seq,
    const float* __restrict__ asrc_mo,  const float* __restrict__ adst_mo,
    const float* __restrict__ att_seq, const float* __restrict__ att_mo,
    const float* __restrict__ z,
    const float* __restrict__ ln_op_g, const float* __restrict__ ln_op_b,
    const float* __restrict__ ln_mac_g, const float* __restrict__ ln_mac_b,
    float* __restrict__ out)
{
    __shared__ __align__(16) float pool[2880];
    int tid = threadIdx.x;
    int w = tid >> 5, lane = tid & 31;
    int head = lane >> 3;
    int f0 = lane * 4;

    if (blockIdx.x < (unsigned)nmac) {
        // ---- mac node (block per node; long blocks scheduled first) ----
        int d = blockIdx.x;
        float* salpha = pool;                 // 320*4
        int*   soff   = (int*)(pool + 1280);  // 320
        float* snum   = pool + 1600;          // 8*32*4
        float* sden   = pool + 2624;          // 8*32

        int c = min(deg_om[d], CAP_MAC);
        float4 ad4 = *(const float4*)(adst_om + (size_t)d * HEADS);
        float af0 = att_om[2 * DK], af1 = att_om[ATT + 2 * DK],
              af2 = att_om[2 * ATT + 2 * DK], af3 = att_om[3 * ATT + 2 * DK];
        for (int e = tid; e < c; e += 256) {
            int2 ed = eb_om[(size_t)d * CAP_MAC + e];
            float4 as = *(const float4*)(asrc_om + (size_t)ed.x * HEADS);
            float f = __int_as_float(ed.y);
            float4 al;
            al.x = lrexp(as.x + ad4.x + f * af0);
            al.y = lrexp(as.y + ad4.y + f * af1);
            al.z = lrexp(as.z + ad4.z + f * af2);
            al.w = lrexp(as.w + ad4.w + f * af3);
            *(float4*)(salpha + e * 4) = al;
            soff[e] = ed.x * OUTF;            // op-row offset, fits in int
        }
        __syncthreads();
        unsigned long long q0 = pack2(0.f, 0.f), q1 = q0;
        float den = 0.f;
#pragma unroll 2
        for (int i = w; i < c; i += 8) {
            float a = salpha[i * 4 + head];
            int o = soff[i];
            ulonglong2 zz = *(const ulonglong2*)(z + o + f0);
            unsigned long long aa = pack2(a, a);
            ffma2(q0, aa, zz.x); ffma2(q1, aa, zz.y);
            den += a;
        }
        float4 num;
        unpack2(q0, num.x, num.y);
        unpack2(q1, num.z, num.w);
        *(float4*)(snum + (w * 32 + lane) * 4) = num;
        sden[w * 32 + lane] = den;
        __syncthreads();
        if (w != 0) return;
        float4 r = *(const float4*)(snum + lane * 4);
        float dn = sden[lane];
#pragma unroll
        for (int ww = 1; ww < 8; ww++) {
            float4 t = *(const float4*)(snum + (ww * 32 + lane) * 4);
            r.x += t.x; r.y += t.y; r.z += t.z; r.w += t.w;
            dn += sden[ww * 32 + lane];
        }
        float inv = 1.f / (dn + EPS);
        float4 v = *(const float4*)(z + ((size_t)N_OP_MAX + d) * OUTF + f0);  // residual
        v.x += r.x * inv; v.y += r.y * inv; v.z += r.z * inv; v.w += r.w * inv;
        ln_elu_store(v, ln_mac_g, ln_mac_b, out + ((size_t)nop + d) * OUTF, f0);
    } else {
        // ---- op nodes (warp per node) ----
        int d = (blockIdx.x - nmac) * 8 + w;
        if (d >= nop) return;
        float* salpha = pool + w * 160;        // 128 alpha + 32 offsets per warp
        int*   soff   = (int*)(salpha + 128);

        float4 v = *(const float4*)(z + (size_t)d * OUTF + f0);  // residual
        float4 c1 = gat_group(d, deg_seq, eb_seq, asrc_seq, adst_seq, att_seq,
                              z, salpha, soff, lane, head, f0);
        v.x += c1.x; v.y += c1.y; v.z += c1.z; v.w += c1.w;
        float4 c2 = gat_group(d, deg_mo, eb_mo, asrc_mo, adst_mo, att_mo,
                              z + (size_t)N_OP_MAX * OUTF, salpha, soff, lane, head, f0);
        v.x += c2.x; v.y += c2.y; v.z += c2.z; v.w += c2.w;
        ln_elu_store(v, ln_op_g, ln_op_b, out + (size_t)d * OUTF, f0);
    }
}

// ---------------- launch ----------------
extern "C" void kernel_launch(void* const* d_in, const int* in_sizes, int n_in,
                              void* d_out, int out_size)
{
    const float* h_op     = (const float*)d_in[0];
    const float* h_mac    = (const float*)d_in[1];
    const int*   seq_src  = (const int*)d_in[2];
    const int*   seq_dst  = (const int*)d_in[3];
    const int*   om_src   = (const int*)d_in[4];
    const int*   om_dst   = (const int*)d_in[5];
    const int*   mo_src   = (const int*)d_in[6];
    const int*   mo_dst   = (const int*)d_in[7];
    const float* feat_seq = (const float*)d_in[8];
    const float* feat_om  = (const float*)d_in[9];
    const float* feat_mo  = (const float*)d_in[10];
    const float* W_op_w   = (const float*)d_in[11];
    const float* W_op_b   = (const float*)d_in[12];
    const float* W_mac_w  = (const float*)d_in[13];
    const float* W_mac_b  = (const float*)d_in[14];
    const float* att_seq  = (const float*)d_in[15];
    const float* att_om   = (const float*)d_in[16];
    const float* att_mo   = (const float*)d_in[17];
    const float* ln_op_g  = (const float*)d_in[18];
    const float* ln_op_b  = (const float*)d_in[19];
    const float* ln_mac_g = (const float*)d_in[20];
    const float* ln_mac_b = (const float*)d_in[21];
    float* out = (float*)d_out;

    int nop  = in_sizes[0] / IN_OP;
    int nmac = in_sizes[1] / IN_MAC;
    int Eseq = in_sizes[2];
    int Eom  = in_sizes[4];
    int Emo  = in_sizes[6];

    float *p_z;
    float *p_asrc_seq, *p_adst_seq, *p_asrc_om, *p_adst_mo, *p_asrc_mo, *p_adst_om;
    int2 *p_eb_seq, *p_eb_mo, *p_eb_om;
    int *p_deg;
    cudaGetSymbolAddress((void**)&p_z,        g_z);
    cudaGetSymbolAddress((void**)&p_asrc_seq, g_asrc_seq);
    cudaGetSymbolAddress((void**)&p_adst_seq, g_adst_seq);
    cudaGetSymbolAddress((void**)&p_asrc_om,  g_asrc_om);
    cudaGetSymbolAddress((void**)&p_adst_mo,  g_adst_mo);
    cudaGetSymbolAddress((void**)&p_asrc_mo,  g_asrc_mo);
    cudaGetSymbolAddress((void**)&p_adst_om,  g_adst_om);
    cudaGetSymbolAddress((void**)&p_eb_seq,   g_eb_seq);
    cudaGetSymbolAddress((void**)&p_eb_mo,    g_eb_mo);
    cudaGetSymbolAddress((void**)&p_eb_om,    g_eb_om);
    cudaGetSymbolAddress((void**)&p_deg,      g_deg);

    int* p_deg_seq = p_deg + DEG_SEQ_OFF;
    int* p_deg_mo  = p_deg + DEG_MO_OFF;
    int* p_deg_om  = p_deg + DEG_OM_OFF;
    float* p_z_mac = p_z + (size_t)N_OP_MAX * OUTF;

    cudaMemsetAsync(p_deg, 0, DEG_TOT * sizeof(int));

    int om_blocks = (Eom + OM_CHUNK - 1) / OM_CHUNK;
    int sm_blocks = (Eseq + Emo + SM_CHUNK - 1) / SM_CHUNK;
    int prep_grid = PRJ_BLOCKS + MAC_BLOCKS + om_blocks + sm_blocks;
    k_prep<<<prep_grid, 256>>>(
        h_op, W_op_w, W_op_b, h_mac, W_mac_w, W_mac_b,
        att_seq, att_om, att_mo, nop, nmac,
        Eseq, Emo, Eom, om_blocks,
        seq_src, seq_dst, feat_seq,
        mo_src, mo_dst, feat_mo,
        om_src, om_dst, feat_om,
        p_z, p_z_mac,
        p_asrc_seq, p_adst_seq, p_asrc_om, p_adst_mo,
        p_asrc_mo, p_adst_om,
        p_deg_seq, p_eb_seq, p_deg_mo, p_eb_mo, p_deg_om, p_eb_om);

    k_nop<<<1, 1>>>();   // spacer: keeps ncu capture slot on k_prep

    int final_grid = nmac + (nop + 7) / 8;
    k_final<<<final_grid, 256>>>(
        nmac, nop,
        p_deg_om, p_eb_om, p_asrc_om, p_adst_om, att_om,
        p_deg_seq, p_eb_seq, p_deg_mo, p_eb_mo,
        p_asrc_seq, p_adst_seq, p_asrc_mo, p_adst_mo,
        att_seq, att_mo,
        p_z,
        ln_op_g, ln_op_b, ln_mac_g, ln_mac_b,
        out);
}

// round 15
// speedup vs baseline: 1.1557x; 1.0091x over previous
#include <cuda_runtime.h>

#define IN_OP   64
#define IN_MAC  32
#define OUTF    128
#define HEADS   4
#define DK      32
#define ATT     65
#define N_OP_MAX   50000
#define N_MAC_MAX  2000
#define CAP_OP  32
#define CAP_MAC 320
#define EPS     1e-6f
#define PRJ_BLOCKS 782
#define MAC_BLOCKS 64
#define OM_CHUNK   8192
#define SM_CHUNK   1024
// XOR swizzle for the transposed weight tile: kills the 32-way STS conflict
// (4-way instead), keeps 16B alignment for ulonglong2 loads, zero smem overhead.
#define SWZ(k, j) ((j) ^ (((k) * 4) & 127))

// ---------------- scratch (device globals; no runtime allocation) ----------------
// unified z: op rows [0, N_OP_MAX), mac rows [N_OP_MAX, N_OP_MAX+N_MAC_MAX)
__device__ __align__(16) float g_z[(N_OP_MAX + N_MAC_MAX) * OUTF];

__device__ __align__(16) float g_asrc_seq[N_OP_MAX  * HEADS];
__device__ __align__(16) float g_adst_seq[N_OP_MAX  * HEADS];
__device__ __align__(16) float g_asrc_om [N_OP_MAX  * HEADS];
__device__ __align__(16) float g_adst_mo [N_OP_MAX  * HEADS];
__device__ __align__(16) float g_asrc_mo [N_MAC_MAX * HEADS];
__device__ __align__(16) float g_adst_om [N_MAC_MAX * HEADS];

// compact per-dst edge buckets: {src, feat_bits}
__device__ __align__(16) int2 g_eb_seq[N_OP_MAX  * CAP_OP];
__device__ __align__(16) int2 g_eb_mo [N_OP_MAX  * CAP_OP];
__device__ __align__(16) int2 g_eb_om [N_MAC_MAX * CAP_MAC];

// degree counters (zeroed by one memset)
#define DEG_SEQ_OFF 0
#define DEG_MO_OFF  N_OP_MAX
#define DEG_OM_OFF  (2 * N_OP_MAX)
#define DEG_TOT     (2 * N_OP_MAX + N_MAC_MAX)
__device__ __align__(16) int g_deg[DEG_TOT];

// ---------------- helpers ----------------
__device__ __forceinline__ float wallred(float v) {
#pragma unroll
    for (int o = 16; o > 0; o >>= 1) v += __shfl_xor_sync(0xffffffffu, v, o);
    return v;
}
__device__ __forceinline__ float wredsum(float v) {
#pragma unroll
    for (int o = 16; o > 0; o >>= 1) v += __shfl_down_sync(0xffffffffu, v, o);
    return v;
}
__device__ __forceinline__ float red8(float v) {
    v += __shfl_xor_sync(0xffffffffu, v, 1);
    v += __shfl_xor_sync(0xffffffffu, v, 2);
    v += __shfl_xor_sync(0xffffffffu, v, 4);
    return v;
}
// leaky_relu(0.2) -> clip(+-20) -> exp
__device__ __forceinline__ float lrexp(float v) {
    v = v > 0.f ? v : 0.2f * v;
    v = fminf(fmaxf(v, -20.f), 20.f);
    return __expf(v);
}
// packed f32x2 (Blackwell FFMA2)
__device__ __forceinline__ unsigned long long pack2(float lo, float hi) {
    unsigned long long r;
    asm("mov.b64 %0, {%1, %2};" : "=l"(r) : "f"(lo), "f"(hi));
    return r;
}
__device__ __forceinline__ void unpack2(unsigned long long v, float& lo, float& hi) {
    asm("mov.b64 {%0, %1}, %2;" : "=f"(lo), "=f"(hi) : "l"(v));
}
__device__ __forceinline__ void ffma2(unsigned long long& d, unsigned long long a,
                                      unsigned long long b) {
    asm("fma.rn.f32x2 %0, %1, %2, %0;" : "+l"(d) : "l"(a), "l"(b));
}
// volatile global load: defeats hoisting so epilogue-only values don't stay live
// across the main loop (register pressure control).
__device__ __forceinline__ float ldg_late(const float* p) {
    float v;
    asm volatile("ld.global.nc.f32 %0, [%1];" : "=f"(v) : "l"(p));
    return v;
}

// ===================== prep kernel blocks =====================

__device__ void proj_op_block(int bid, const float* __restrict__ h, const float* __restrict__ W,
                              const float* __restrict__ bias,
                              const float* __restrict__ att_seq, const float* __restrict__ att_om,
                              const float* __restrict__ att_mo, int n,
                              float* __restrict__ z,
                              float* __restrict__ asrc_seq, float* __restrict__ adst_seq,
                              float* __restrict__ asrc_om,  float* __restrict__ adst_mo,
                              float* pool)
{
    float* sW = pool;                 // 8192 floats, transposed+swizzled: sW[k*128 + SWZ(k,j)]
    float* sh = pool + IN_OP * OUTF;  // 4096 floats (64 nodes x 64)
    int tid = threadIdx.x;
    int warp = tid >> 5, lane = tid & 31;
    for (int i = tid; i < IN_OP * OUTF; i += 256) {
        int j = i >> 6, k = i & 63;
        sW[k * OUTF + SWZ(k, j)] = W[i];   // 4-way store conflict, not 32-way
    }
    int f0 = lane * 4;
    int head = lane >> 3;
    int dk = f0 & 31;
    float4 bj = *(const float4*)(bias + f0);
    unsigned long long bj0 = pack2(bj.x, bj.y), bj1 = pack2(bj.z, bj.w);

    for (int n0 = bid * 64; n0 < n; n0 += PRJ_BLOCKS * 64) {
        int cnt = min(n - n0, 64);
        __syncthreads();
        // vectorized h tile fill: LDG.128 + STS.128, conflict-free both sides
        {
            int total = cnt * IN_OP;
            for (int i = tid * 4; i < total; i += 1024)
                *(float4*)(sh + i) = *(const float4*)(h + (size_t)n0 * IN_OP + i);
        }
        __syncthreads();
        unsigned long long acc[8][2];
#pragma unroll
        for (int r = 0; r < 8; r++) { acc[r][0] = bj0; acc[r][1] = bj1; }
        int base = warp * 8;
#pragma unroll 1
        for (int k4 = 0; k4 < IN_OP; k4 += 4) {
            // swizzled offset is a row-constant multiple of 4 -> 16B-aligned, conflict-free
            ulonglong2 w0 = *(const ulonglong2*)(sW + (k4 + 0) * OUTF + SWZ(k4 + 0, f0));
            ulonglong2 w1 = *(const ulonglong2*)(sW + (k4 + 1) * OUTF + SWZ(k4 + 1, f0));
            ulonglong2 w2 = *(const ulonglong2*)(sW + (k4 + 2) * OUTF + SWZ(k4 + 2, f0));
            ulonglong2 w3 = *(const ulonglong2*)(sW + (k4 + 3) * OUTF + SWZ(k4 + 3, f0));
#pragma unroll
            for (int r = 0; r < 8; r++) {
                float4 hv = *(const float4*)(sh + (base + r) * IN_OP + k4);  // broadcast
                unsigned long long hx = pack2(hv.x, hv.x);
                unsigned long long hy = pack2(hv.y, hv.y);
                unsigned long long hz = pack2(hv.z, hv.z);
                unsigned long long hw = pack2(hv.w, hv.w);
                ffma2(acc[r][0], hx, w0.x); ffma2(acc[r][1], hx, w0.y);
                ffma2(acc[r][0], hy, w1.x); ffma2(acc[r][1], hy, w1.y);
                ffma2(acc[r][0], hz, w2.x); ffma2(acc[r][1], hz, w2.y);
                ffma2(acc[r][0], hw, w3.x); ffma2(acc[r][1], hw, w3.y);
            }
        }
        // epilogue: load att coeffs LATE (volatile -> not live across the k-loop)
        float a_s1[4], a_d1[4], a_s3[4], a_d4[4];
#pragma unroll
        for (int i = 0; i < 4; i++) {
            a_s1[i] = ldg_late(att_seq + head * ATT + dk + i);
            a_d1[i] = ldg_late(att_seq + head * ATT + DK + dk + i);
            a_s3[i] = ldg_late(att_om  + head * ATT + dk + i);
            a_d4[i] = ldg_late(att_mo  + head * ATT + DK + dk + i);
        }
#pragma unroll
        for (int r = 0; r < 8; r++) {
            int node = n0 + base + r;
            if (base + r >= cnt) break;   // uniform across warp
            float4 zz;
            unpack2(acc[r][0], zz.x, zz.y);
            unpack2(acc[r][1], zz.z, zz.w);
            // SWZ is an involution: each thread accumulated its own logical cols f0..f0+3
            *(float4*)(z + (size_t)node * OUTF + f0) = zz;
            float p1 = zz.x * a_s1[0] + zz.y * a_s1[1] + zz.z * a_s1[2] + zz.w * a_s1[3];
            float p2 = zz.x * a_d1[0] + zz.y * a_d1[1] + zz.z * a_d1[2] + zz.w * a_d1[3];
            float p3 = zz.x * a_s3[0] + zz.y * a_s3[1] + zz.z * a_s3[2] + zz.w * a_s3[3];
            float p4 = zz.x * a_d4[0] + zz.y * a_d4[1] + zz.z * a_d4[2] + zz.w * a_d4[3];
            p1 = red8(p1); p2 = red8(p2); p3 = red8(p3); p4 = red8(p4);
            if ((lane & 7) == 0) {
                asrc_seq[node * HEADS + head] = p1;
                adst_seq[node * HEADS + head] = p2;
                asrc_om [node * HEADS + head] = p3;
                adst_mo [node * HEADS + head] = p4;
            }
        }
    }
}

__device__ void proj_mac_block(int mbid, const float* __restrict__ h, const float* __restrict__ W,
                               const float* __restrict__ bias,
                               const float* __restrict__ att_mo, const float* __restrict__ att_om,
                               int n, float* __restrict__ z,   // z already offset to mac region
                               float* __restrict__ asrc_mo, float* __restrict__ adst_om,
                               float* pool)
{
    float* sW = pool;                  // 4096 floats, swizzled
    float* sh = pool + IN_MAC * OUTF;  // 64 floats (2 nodes x 32)
    int tid = threadIdx.x;
    for (int i = tid; i < IN_MAC * OUTF; i += 256) {
        int j = i >> 5, k = i & 31;
        sW[k * OUTF + SWZ(k, j)] = W[i];
    }
    int wg = tid >> 7, wtid = tid & 127;
    int head = wtid >> 5, lane = wtid & 31;
    float a1 = att_mo[head * ATT + lane];
    float a2 = att_om[head * ATT + DK + lane];
    float bj = bias[wtid];
    for (int n0 = mbid * 2; n0 < n; n0 += MAC_BLOCKS * 2) {
        int cnt = min(n - n0, 2);
        __syncthreads();
        for (int i = tid; i < cnt * IN_MAC; i += 256) sh[i] = h[(size_t)n0 * IN_MAC + i];
        __syncthreads();
        int node = n0 + wg;
        if (node < n) {
            float zz = bj;
#pragma unroll
            for (int k = 0; k < IN_MAC; k++)
                zz += sh[wg * IN_MAC + k] * sW[k * OUTF + SWZ(k, wtid)];
            z[(size_t)node * OUTF + wtid] = zz;
            float s1 = wredsum(zz * a1);
            float s2 = wredsum(zz * a2);
            if (lane == 0) {
                asrc_mo[node * HEADS + head] = s1;
                adst_om[node * HEADS + head] = s2;
            }
        }
    }
}

// CTA-aggregated om bucketing: per-block smem counts -> one global atomic per
// distinct dst per block -> smem-slot scatter.
__device__ void bucket_om_block(int ob, int E, int nmac,
                                const int* __restrict__ src, const int* __restrict__ dst,
                                const float* __restrict__ feat,
                                int* __restrict__ deg, int2* __restrict__ eb,
                                float* pool)
{
    int* scnt  = (int*)pool;           // nmac counters
    int* sbase = (int*)pool + N_MAC_MAX;
    int tid = threadIdx.x;
    int e0 = ob * OM_CHUNK;
    int e1 = min(e0 + OM_CHUNK, E);
    for (int i = tid; i < nmac; i += 256) scnt[i] = 0;
    __syncthreads();
    for (int e = e0 + tid; e < e1; e += 256) atomicAdd(scnt + dst[e], 1);
    __syncthreads();
    for (int i = tid; i < nmac; i += 256) {
        int c = scnt[i];
        sbase[i] = c ? atomicAdd(deg + i, c) : 0;
        scnt[i] = 0;
    }
    __syncthreads();
    for (int e = e0 + tid; e < e1; e += 256) {
        int d = dst[e];
        int slot = sbase[d] + atomicAdd(scnt + d, 1);
        if (slot < CAP_MAC)
            eb[(size_t)d * CAP_MAC + slot] = make_int2(src[e], __float_as_int(feat[e]));
    }
}

// seq+mo edges: op dsts (50k) -> low contention, direct atomics, 4 edges/thread
__device__ void bucket_sm_block(int sb, int Ea, int Eb,
                                const int* __restrict__ sa, const int* __restrict__ da,
                                const float* __restrict__ fa,
                                const int* __restrict__ sb_, const int* __restrict__ db,
                                const float* __restrict__ fb,
                                int* __restrict__ dega, int2* __restrict__ eba,
                                int* __restrict__ degb, int2* __restrict__ ebb)
{
    int tid = threadIdx.x;
#pragma unroll
    for (int r = 0; r < 4; r++) {
        int e = sb * SM_CHUNK + r * 256 + tid;
        if (e < Ea) {
            int s = sa[e], d = da[e];
            float f = fa[e];
            int slot = atomicAdd(dega + d, 1);
            if (slot < CAP_OP) eba[(size_t)d * CAP_OP + slot] = make_int2(s, __float_as_int(f));
        } else if (e < Ea + Eb) {
            int ee = e - Ea;
            int s = sb_[ee], d = db[ee];
            float f = fb[ee];
            int slot = atomicAdd(degb + d, 1);
            if (slot < CAP_OP) ebb[(size_t)d * CAP_OP + slot] = make_int2(s, __float_as_int(f));
        }
    }
}

__global__ __launch_bounds__(256, 4) void k_prep(
    const float* h_op, const float* W_op_w, const float* W_op_b,
    const float* h_mac, const float* W_mac_w, const float* W_mac_b,
    const float* att_seq, const float* att_om, const float* att_mo,
    int nop, int nmac,
    int Eseq, int Emo, int Eom, int om_blocks,
    const int* seq_src, const int* seq_dst, const float* feat_seq,
    const int* mo_src,  const int* mo_dst,  const float* feat_mo,
    const int* om_src,  const int* om_dst,  const float* feat_om,
    float* z, float* z_mac,
    float* asrc_seq, float* adst_seq, float* asrc_om, float* adst_mo,
    float* asrc_mo, float* adst_om,
    int* deg_seq, int2* eb_seq, int* deg_mo, int2* eb_mo, int* deg_om, int2* eb_om)
{
    __shared__ __align__(16) float pool[IN_OP * OUTF + 64 * IN_OP];  // 48 KB
    int bid = blockIdx.x;
    if (bid < PRJ_BLOCKS) {
        proj_op_block(bid, h_op, W_op_w, W_op_b, att_seq, att_om, att_mo, nop,
                      z, asrc_seq, adst_seq, asrc_om, adst_mo, pool);
    } else if (bid < PRJ_BLOCKS + MAC_BLOCKS) {
        proj_mac_block(bid - PRJ_BLOCKS, h_mac, W_mac_w, W_mac_b, att_mo, att_om, nmac,
                       z_mac, asrc_mo, adst_om, pool);
    } else if (bid < PRJ_BLOCKS + MAC_BLOCKS + om_blocks) {
        bucket_om_block(bid - PRJ_BLOCKS - MAC_BLOCKS, Eom, nmac,
                        om_src, om_dst, feat_om, deg_om, eb_om, pool);
    } else {
        bucket_sm_block(bid - PRJ_BLOCKS - MAC_BLOCKS - om_blocks, Eseq, Emo,
                        seq_src, seq_dst, feat_seq,
                        mo_src, mo_dst, feat_mo,
                        deg_seq, eb_seq, deg_mo, eb_mo);
    }
}

// diagnostic spacer: shifts ncu's fixed capture index onto k_prep
__global__ void k_nop() {}

// ===================== final kernel =====================

// per-warp gather for one edge group of an op node; returns normalized contribution.
// soff holds precomputed row offsets (src*OUTF) -> 32-bit add in hot loop, no IMAD.wide.
__device__ __forceinline__ float4 gat_group(int d, const int* __restrict__ deg,
                                            const int2* __restrict__ eb,
                                            const float* __restrict__ asrc,
                                            const float* __restrict__ adst,
                                            const float* __restrict__ att,
                                            const float* __restrict__ z,
                                            float* salpha, int* soff,
                                            int lane, int head, int f0)
{
    float4 res = make_float4(0.f, 0.f, 0.f, 0.f);
    int cs = min(deg[d], CAP_OP);
    if (cs == 0) return res;
    float4 ad4 = *(const float4*)(adst + (size_t)d * HEADS);
    float af0 = att[2 * DK], af1 = att[ATT + 2 * DK], af2 = att[2 * ATT + 2 * DK],
          af3 = att[3 * ATT + 2 * DK];
    if (lane < cs) {
        int2 ed = eb[(size_t)d * CAP_OP + lane];
        float4 as = *(const float4*)(asrc + (size_t)ed.x * HEADS);
        float f = __int_as_float(ed.y);
        float4 al;
        al.x = lrexp(as.x + ad4.x + f * af0);
        al.y = lrexp(as.y + ad4.y + f * af1);
        al.z = lrexp(as.z + ad4.z + f * af2);
        al.w = lrexp(as.w + ad4.w + f * af3);
        *(float4*)(salpha + lane * 4) = al;
        soff[lane] = ed.x * OUTF;
    }
    __syncwarp();
    unsigned long long n0 = pack2(0.f, 0.f), n1 = n0;
    float den = 0.f;
#pragma unroll 4
    for (int i = 0; i < cs; i++) {
        float a = salpha[i * 4 + head];
        int o = soff[i];
        ulonglong2 zz = *(const ulonglong2*)(z + o + f0);
        unsigned long long aa = pack2(a, a);
        ffma2(n0, aa, zz.x); ffma2(n1, aa, zz.y);
        den += a;
    }
    __syncwarp();
    float inv = 1.f / (den + EPS);
    float x0, x1, x2, x3;
    unpack2(n0, x0, x1);
    unpack2(n1, x2, x3);
    res.x = x0 * inv; res.y = x1 * inv; res.z = x2 * inv; res.w = x3 * inv;
    return res;
}

__device__ __forceinline__ void ln_elu_store(float4 v, const float* g, const float* b,
                                             float* out, int f0)
{
    float s0 = wallred(v.x + v.y + v.z + v.w);
    float mu = s0 * (1.f / OUTF);
    float d0 = v.x - mu, d1 = v.y - mu, d2 = v.z - mu, d3 = v.w - mu;
    float var = wallred(d0 * d0 + d1 * d1 + d2 * d2 + d3 * d3);
    float rs = rsqrtf(var * (1.f / OUTF) + 1e-5f);
    float4 gg = *(const float4*)(g + f0);
    float4 bb = *(const float4*)(b + f0);
    float4 y;
    y.x = d0 * rs * gg.x + bb.x;
    y.y = d1 * rs * gg.y + bb.y;
    y.z = d2 * rs * gg.z + bb.z;
    y.w = d3 * rs * gg.w + bb.w;
    y.x = y.x > 0.f ? y.x : __expf(y.x) - 1.f;
    y.y = y.y > 0.f ? y.y : __expf(y.y) - 1.f;
    y.z = y.z > 0.f ? y.z : __expf(y.z) - 1.f;
    y.w = y.w > 0.f ? y.w : __expf(y.w) - 1.f;
    *(float4*)(out + f0) = y;
}

__global__ __launch_bounds__(256) void k_final(
    int nmac, int nop,
    const int* __restrict__ deg_om, const int2* __restrict__ eb_om,
    const float* __restrict__ asrc_om, const float* __restrict__ adst_om,
    const float* __restrict__ att_om,
    const int* __restrict__ deg_seq, const int2* __restrict__ eb_seq,
    const int* __restrict__ deg_mo,  const int2* __restrict__ eb_mo,
    const float* __restrict__ asrc_seq, const float* __restrict__ adst_seq,
    const float* __restrict__ asrc_mo,  const float* __restrict__ adst_mo,
    const float* __restrict__ att_seq, const float* __restrict__ att_mo,
    const float* __restrict__ z,
    const float* __restrict__ ln_op_g, const float* __restrict__ ln_op_b,
    const float* __restrict__ ln_mac_g, const float* __restrict__ ln_mac_b,
    float* __restrict__ out)
{
    __shared__ __align__(16) float pool[2880];
    int tid = threadIdx.x;
    int w = tid >> 5, lane = tid & 31;
    int head = lane >> 3;
    int f0 = lane * 4;

    if (blockIdx.x < (unsigned)nmac) {
        // ---- mac node (block per node; long blocks scheduled first) ----
        int d = blockIdx.x;
        float* salpha = pool;                 // 320*4
        int*   soff   = (int*)(pool + 1280);  // 320
        float* snum   = pool + 1600;          // 8*32*4
        float* sden   = pool + 2624;          // 8*32

        int c = min(deg_om[d], CAP_MAC);
        float4 ad4 = *(const float4*)(adst_om + (size_t)d * HEADS);
        float af0 = att_om[2 * DK], af1 = att_om[ATT + 2 * DK],
              af2 = att_om[2 * ATT + 2 * DK], af3 = att_om[3 * ATT + 2 * DK];
        for (int e = tid; e < c; e += 256) {
            int2 ed = eb_om[(size_t)d * CAP_MAC + e];
            float4 as = *(const float4*)(asrc_om + (size_t)ed.x * HEADS);
            float f = __int_as_float(ed.y);
            float4 al;
            al.x = lrexp(as.x + ad4.x + f * af0);
            al.y = lrexp(as.y + ad4.y + f * af1);
            al.z = lrexp(as.z + ad4.z + f * af2);
            al.w = lrexp(as.w + ad4.w + f * af3);
            *(float4*)(salpha + e * 4) = al;
            soff[e] = ed.x * OUTF;            // op-row offset, fits in int
        }
        __syncthreads();
        unsigned long long q0 = pack2(0.f, 0.f), q1 = q0;
        float den = 0.f;
#pragma unroll 2
        for (int i = w; i < c; i += 8) {
            float a = salpha[i * 4 + head];
            int o = soff[i];
            ulonglong2 zz = *(const ulonglong2*)(z + o + f0);
            unsigned long long aa = pack2(a, a);
            ffma2(q0, aa, zz.x); ffma2(q1, aa, zz.y);
            den += a;
        }
        float4 num;
        unpack2(q0, num.x, num.y);
        unpack2(q1, num.z, num.w);
        *(float4*)(snum + (w * 32 + lane) * 4) = num;
        sden[w * 32 + lane] = den;
        __syncthreads();
        if (w != 0) return;
        float4 r = *(const float4*)(snum + lane * 4);
        float dn = sden[lane];
#pragma unroll
        for (int ww = 1; ww < 8; ww++) {
            float4 t = *(const float4*)(snum + (ww * 32 + lane) * 4);
            r.x += t.x; r.y += t.y; r.z += t.z; r.w += t.w;
            dn += sden[ww * 32 + lane];
        }
        float inv = 1.f / (dn + EPS);
        float4 v = *(const float4*)(z + ((size_t)N_OP_MAX + d) * OUTF + f0);  // residual
        v.x += r.x * inv; v.y += r.y * inv; v.z += r.z * inv; v.w += r.w * inv;
        ln_elu_store(v, ln_mac_g, ln_mac_b, out + ((size_t)nop + d) * OUTF, f0);
    } else {
        // ---- op nodes (warp per node) ----
        int d = (blockIdx.x - nmac) * 8 + w;
        if (d >= nop) return;
        float* salpha = pool + w * 160;        // 128 alpha + 32 offsets per warp
        int*   soff   = (int*)(salpha + 128);

        float4 v = *(const float4*)(z + (size_t)d * OUTF + f0);  // residual
        float4 c1 = gat_group(d, deg_seq, eb_seq, asrc_seq, adst_seq, att_seq,
                              z, salpha, soff, lane, head, f0);
        v.x += c1.x; v.y += c1.y; v.z += c1.z; v.w += c1.w;
        float4 c2 = gat_group(d, deg_mo, eb_mo, asrc_mo, adst_mo, att_mo,
                              z + (size_t)N_OP_MAX * OUTF, salpha, soff, lane, head, f0);
        v.x += c2.x; v.y += c2.y; v.z += c2.z; v.w += c2.w;
        ln_elu_store(v, ln_op_g, ln_op_b, out + (size_t)d * OUTF, f0);
    }
}

// ---------------- launch ----------------
extern "C" void kernel_launch(void* const* d_in, const int* in_sizes, int n_in,
                              void* d_out, int out_size)
{
    const float* h_op     = (const float*)d_in[0];
    const float* h_mac    = (const float*)d_in[1];
    const int*   seq_src  = (const int*)d_in[2];
    const int*   seq_dst  = (const int*)d_in[3];
    const int*   om_src   = (const int*)d_in[4];
    const int*   om_dst   = (const int*)d_in[5];
    const int*   mo_src   = (const int*)d_in[6];
    const int*   mo_dst   = (const int*)d_in[7];
    const float* feat_seq = (const float*)d_in[8];
    const float* feat_om  = (const float*)d_in[9];
    const float* feat_mo  = (const float*)d_in[10];
    const float* W_op_w   = (const float*)d_in[11];
    const float* W_op_b   = (const float*)d_in[12];
    const float* W_mac_w  = (const float*)d_in[13];
    const float* W_mac_b  = (const float*)d_in[14];
    const float* att_seq  = (const float*)d_in[15];
    const float* att_om   = (const float*)d_in[16];
    const float* att_mo   = (const float*)d_in[17];
    const float* ln_op_g  = (const float*)d_in[18];
    const float* ln_op_b  = (const float*)d_in[19];
    const float* ln_mac_g = (const float*)d_in[20];
    const float* ln_mac_b = (const float*)d_in[21];
    float* out = (float*)d_out;

    int nop  = in_sizes[0] / IN_OP;
    int nmac = in_sizes[1] / IN_MAC;
    int Eseq = in_sizes[2];
    int Eom  = in_sizes[4];
    int Emo  = in_sizes[6];

    float *p_z;
    float *p_asrc_seq, *p_adst_seq, *p_asrc_om, *p_adst_mo, *p_asrc_mo, *p_adst_om;
    int2 *p_eb_seq, *p_eb_mo, *p_eb_om;
    int *p_deg;
    cudaGetSymbolAddress((void**)&p_z,        g_z);
    cudaGetSymbolAddress((void**)&p_asrc_seq, g_asrc_seq);
    cudaGetSymbolAddress((void**)&p_adst_seq, g_adst_seq);
    cudaGetSymbolAddress((void**)&p_asrc_om,  g_asrc_om);
    cudaGetSymbolAddress((void**)&p_adst_mo,  g_adst_mo);
    cudaGetSymbolAddress((void**)&p_asrc_mo,  g_asrc_mo);
    cudaGetSymbolAddress((void**)&p_adst_om,  g_adst_om);
    cudaGetSymbolAddress((void**)&p_eb_seq,   g_eb_seq);
    cudaGetSymbolAddress((void**)&p_eb_mo,    g_eb_mo);
    cudaGetSymbolAddress((void**)&p_eb_om,    g_eb_om);
    cudaGetSymbolAddress((void**)&p_deg,      g_deg);

    int* p_deg_seq = p_deg + DEG_SEQ_OFF;
    int* p_deg_mo  = p_deg + DEG_MO_OFF;
    int* p_deg_om  = p_deg + DEG_OM_OFF;
    float* p_z_mac = p_z + (size_t)N_OP_MAX * OUTF;

    cudaMemsetAsync(p_deg, 0, DEG_TOT * sizeof(int));

    int om_blocks = (Eom + OM_CHUNK - 1) / OM_CHUNK;
    int sm_blocks = (Eseq + Emo + SM_CHUNK - 1) / SM_CHUNK;
    int prep_grid = PRJ_BLOCKS + MAC_BLOCKS + om_blocks + sm_blocks;
    k_prep<<<prep_grid, 256>>>(
        h_op, W_op_w, W_op_b, h_mac, W_mac_w, W_mac_b,
        att_seq, att_om, att_mo, nop, nmac,
        Eseq, Emo, Eom, om_blocks,
        seq_src, seq_dst, feat_seq,
        mo_src, mo_dst, feat_mo,
        om_src, om_dst, feat_om,
        p_z, p_z_mac,
        p_asrc_seq, p_adst_seq, p_asrc_om, p_adst_mo,
        p_asrc_mo, p_adst_om,
        p_deg_seq, p_eb_seq, p_deg_mo, p_eb_mo, p_deg_om, p_eb_om);

    k_nop<<<1, 1>>>();   // spacer: keeps ncu capture slot on k_prep

    int final_grid = nmac + (nop + 7) / 8;
    k_final<<<final_grid, 256>>>(
        nmac, nop,
        p_deg_om, p_eb_om, p_asrc_om, p_adst_om, att_om,
        p_deg_seq, p_eb_seq, p_deg_mo, p_eb_mo,
        p_asrc_seq, p_adst_seq, p_asrc_mo, p_adst_mo,
        att_seq, att_mo,
        p_z,
        ln_op_g, ln_op_b, ln_mac_g, ln_mac_b,
        out);
}

// round 16
// speedup vs baseline: 1.2508x; 1.0823x over previous
#include <cuda_runtime.h>

#define IN_OP   64
#define IN_MAC  32
#define OUTF    128
#define HEADS   4
#define DK      32
#define ATT     65
#define N_OP_MAX   50000
#define N_MAC_MAX  2000
#define CAP_OP  32
#define CAP_MAC 320
#define EPS     1e-6f
#define PRJ_BLOCKS 782
#define MAC_BLOCKS 64
#define OM_CHUNK   8192
#define SM_CHUNK   1024
// XOR swizzle for the transposed weight tile: kills the 32-way STS conflict
// (4-way instead), keeps 16B alignment for ulonglong2 loads, zero smem overhead.
#define SWZ(k, j) ((j) ^ (((k) * 4) & 127))

// ---------------- scratch (device globals; no runtime allocation) ----------------
// unified z: op rows [0, N_OP_MAX), mac rows [N_OP_MAX, N_OP_MAX+N_MAC_MAX)
__device__ __align__(16) float g_z[(N_OP_MAX + N_MAC_MAX) * OUTF];

__device__ __align__(16) float g_asrc_seq[N_OP_MAX  * HEADS];
__device__ __align__(16) float g_adst_seq[N_OP_MAX  * HEADS];
__device__ __align__(16) float g_asrc_om [N_OP_MAX  * HEADS];
__device__ __align__(16) float g_adst_mo [N_OP_MAX  * HEADS];
__device__ __align__(16) float g_asrc_mo [N_MAC_MAX * HEADS];
__device__ __align__(16) float g_adst_om [N_MAC_MAX * HEADS];

// compact per-dst edge buckets: {src, feat_bits}
__device__ __align__(16) int2 g_eb_seq[N_OP_MAX  * CAP_OP];
__device__ __align__(16) int2 g_eb_mo [N_OP_MAX  * CAP_OP];
__device__ __align__(16) int2 g_eb_om [N_MAC_MAX * CAP_MAC];

// degree counters (zeroed by one memset)
#define DEG_SEQ_OFF 0
#define DEG_MO_OFF  N_OP_MAX
#define DEG_OM_OFF  (2 * N_OP_MAX)
#define DEG_TOT     (2 * N_OP_MAX + N_MAC_MAX)
__device__ __align__(16) int g_deg[DEG_TOT];

// ---------------- helpers ----------------
__device__ __forceinline__ float wallred(float v) {
#pragma unroll
    for (int o = 16; o > 0; o >>= 1) v += __shfl_xor_sync(0xffffffffu, v, o);
    return v;
}
__device__ __forceinline__ float wredsum(float v) {
#pragma unroll
    for (int o = 16; o > 0; o >>= 1) v += __shfl_down_sync(0xffffffffu, v, o);
    return v;
}
__device__ __forceinline__ float red8(float v) {
    v += __shfl_xor_sync(0xffffffffu, v, 1);
    v += __shfl_xor_sync(0xffffffffu, v, 2);
    v += __shfl_xor_sync(0xffffffffu, v, 4);
    return v;
}
// leaky_relu(0.2) -> clip(+-20) -> exp
__device__ __forceinline__ float lrexp(float v) {
    v = v > 0.f ? v : 0.2f * v;
    v = fminf(fmaxf(v, -20.f), 20.f);
    return __expf(v);
}
// packed f32x2 (Blackwell FFMA2)
__device__ __forceinline__ unsigned long long pack2(float lo, float hi) {
    unsigned long long r;
    asm("mov.b64 %0, {%1, %2};" : "=l"(r) : "f"(lo), "f"(hi));
    return r;
}
__device__ __forceinline__ void unpack2(unsigned long long v, float& lo, float& hi) {
    asm("mov.b64 {%0, %1}, %2;" : "=f"(lo), "=f"(hi) : "l"(v));
}
__device__ __forceinline__ void ffma2(unsigned long long& d, unsigned long long a,
                                      unsigned long long b) {
    asm("fma.rn.f32x2 %0, %1, %2, %0;" : "+l"(d) : "l"(a), "l"(b));
}
// volatile global load: defeats hoisting so epilogue-only values don't stay live
// across the main loop (register pressure control).
__device__ __forceinline__ float ldg_late(const float* p) {
    float v;
    asm volatile("ld.global.nc.f32 %0, [%1];" : "=f"(v) : "l"(p));
    return v;
}

// ===================== prep kernel blocks =====================

__device__ void proj_op_block(int bid, const float* __restrict__ h, const float* __restrict__ W,
                              const float* __restrict__ bias,
                              const float* __restrict__ att_seq, const float* __restrict__ att_om,
                              const float* __restrict__ att_mo, int n,
                              float* __restrict__ z,
                              float* __restrict__ asrc_seq, float* __restrict__ adst_seq,
                              float* __restrict__ asrc_om,  float* __restrict__ adst_mo,
                              float* pool)
{
    float* sW = pool;                 // 8192 floats, transposed+swizzled: sW[k*128 + SWZ(k,j)]
    float* sh = pool + IN_OP * OUTF;  // 4096 floats (64 nodes x 64)
    int tid = threadIdx.x;
    int warp = tid >> 5, lane = tid & 31;
    for (int i = tid; i < IN_OP * OUTF; i += 256) {
        int j = i >> 6, k = i & 63;
        sW[k * OUTF + SWZ(k, j)] = W[i];   // 4-way store conflict, not 32-way
    }
    int f0 = lane * 4;
    int head = lane >> 3;
    int dk = f0 & 31;
    float4 bj = *(const float4*)(bias + f0);
    unsigned long long bj0 = pack2(bj.x, bj.y), bj1 = pack2(bj.z, bj.w);

    for (int n0 = bid * 64; n0 < n; n0 += PRJ_BLOCKS * 64) {
        int cnt = min(n - n0, 64);
        __syncthreads();
        // vectorized h tile fill: LDG.128 + STS.128, conflict-free both sides
        {
            int total = cnt * IN_OP;
            for (int i = tid * 4; i < total; i += 1024)
                *(float4*)(sh + i) = *(const float4*)(h + (size_t)n0 * IN_OP + i);
        }
        __syncthreads();
        unsigned long long acc[8][2];
#pragma unroll
        for (int r = 0; r < 8; r++) { acc[r][0] = bj0; acc[r][1] = bj1; }
        int base = warp * 8;
#pragma unroll 1
        for (int k4 = 0; k4 < IN_OP; k4 += 4) {
            // swizzled offset is a row-constant multiple of 4 -> 16B-aligned, conflict-free
            ulonglong2 w0 = *(const ulonglong2*)(sW + (k4 + 0) * OUTF + SWZ(k4 + 0, f0));
            ulonglong2 w1 = *(const ulonglong2*)(sW + (k4 + 1) * OUTF + SWZ(k4 + 1, f0));
            ulonglong2 w2 = *(const ulonglong2*)(sW + (k4 + 2) * OUTF + SWZ(k4 + 2, f0));
            ulonglong2 w3 = *(const ulonglong2*)(sW + (k4 + 3) * OUTF + SWZ(k4 + 3, f0));
#pragma unroll
            for (int r = 0; r < 8; r++) {
                float4 hv = *(const float4*)(sh + (base + r) * IN_OP + k4);  // broadcast
                unsigned long long hx = pack2(hv.x, hv.x);
                unsigned long long hy = pack2(hv.y, hv.y);
                unsigned long long hz = pack2(hv.z, hv.z);
                unsigned long long hw = pack2(hv.w, hv.w);
                ffma2(acc[r][0], hx, w0.x); ffma2(acc[r][1], hx, w0.y);
                ffma2(acc[r][0], hy, w1.x); ffma2(acc[r][1], hy, w1.y);
                ffma2(acc[r][0], hz, w2.x); ffma2(acc[r][1], hz, w2.y);
                ffma2(acc[r][0], hw, w3.x); ffma2(acc[r][1], hw, w3.y);
            }
        }
        // epilogue: load att coeffs LATE (volatile -> not live across the k-loop)
        float a_s1[4], a_d1[4], a_s3[4], a_d4[4];
#pragma unroll
        for (int i = 0; i < 4; i++) {
            a_s1[i] = ldg_late(att_seq + head * ATT + dk + i);
            a_d1[i] = ldg_late(att_seq + head * ATT + DK + dk + i);
            a_s3[i] = ldg_late(att_om  + head * ATT + dk + i);
            a_d4[i] = ldg_late(att_mo  + head * ATT + DK + dk + i);
        }
#pragma unroll
        for (int r = 0; r < 8; r++) {
            int node = n0 + base + r;
            if (base + r >= cnt) break;   // uniform across warp
            float4 zz;
            unpack2(acc[r][0], zz.x, zz.y);
            unpack2(acc[r][1], zz.z, zz.w);
            // SWZ is an involution: each thread accumulated its own logical cols f0..f0+3
            *(float4*)(z + (size_t)node * OUTF + f0) = zz;
            float p1 = zz.x * a_s1[0] + zz.y * a_s1[1] + zz.z * a_s1[2] + zz.w * a_s1[3];
            float p2 = zz.x * a_d1[0] + zz.y * a_d1[1] + zz.z * a_d1[2] + zz.w * a_d1[3];
            float p3 = zz.x * a_s3[0] + zz.y * a_s3[1] + zz.z * a_s3[2] + zz.w * a_s3[3];
            float p4 = zz.x * a_d4[0] + zz.y * a_d4[1] + zz.z * a_d4[2] + zz.w * a_d4[3];
            p1 = red8(p1); p2 = red8(p2); p3 = red8(p3); p4 = red8(p4);
            if ((lane & 7) == 0) {
                asrc_seq[node * HEADS + head] = p1;
                adst_seq[node * HEADS + head] = p2;
                asrc_om [node * HEADS + head] = p3;
                adst_mo [node * HEADS + head] = p4;
            }
        }
    }
}

__device__ void proj_mac_block(int mbid, const float* __restrict__ h, const float* __restrict__ W,
                               const float* __restrict__ bias,
                               const float* __restrict__ att_mo, const float* __restrict__ att_om,
                               int n, float* __restrict__ z,   // z already offset to mac region
                               float* __restrict__ asrc_mo, float* __restrict__ adst_om,
                               float* pool)
{
    float* sW = pool;                  // 4096 floats, swizzled
    float* sh = pool + IN_MAC * OUTF;  // 64 floats (2 nodes x 32)
    int tid = threadIdx.x;
    for (int i = tid; i < IN_MAC * OUTF; i += 256) {
        int j = i >> 5, k = i & 31;
        sW[k * OUTF + SWZ(k, j)] = W[i];
    }
    int wg = tid >> 7, wtid = tid & 127;
    int head = wtid >> 5, lane = wtid & 31;
    float a1 = att_mo[head * ATT + lane];
    float a2 = att_om[head * ATT + DK + lane];
    float bj = bias[wtid];
    for (int n0 = mbid * 2; n0 < n; n0 += MAC_BLOCKS * 2) {
        int cnt = min(n - n0, 2);
        __syncthreads();
        for (int i = tid; i < cnt * IN_MAC; i += 256) sh[i] = h[(size_t)n0 * IN_MAC + i];
        __syncthreads();
        int node = n0 + wg;
        if (node < n) {
            float zz = bj;
#pragma unroll
            for (int k = 0; k < IN_MAC; k++)
                zz += sh[wg * IN_MAC + k] * sW[k * OUTF + SWZ(k, wtid)];
            z[(size_t)node * OUTF + wtid] = zz;
            float s1 = wredsum(zz * a1);
            float s2 = wredsum(zz * a2);
            if (lane == 0) {
                asrc_mo[node * HEADS + head] = s1;
                adst_om[node * HEADS + head] = s2;
            }
        }
    }
}

// CTA-aggregated om bucketing: per-block smem counts -> one global atomic per
// distinct dst per block -> smem-slot scatter.
__device__ void bucket_om_block(int ob, int E, int nmac,
                                const int* __restrict__ src, const int* __restrict__ dst,
                                const float* __restrict__ feat,
                                int* __restrict__ deg, int2* __restrict__ eb,
                                float* pool)
{
    int* scnt  = (int*)pool;           // nmac counters
    int* sbase = (int*)pool + N_MAC_MAX;
    int tid = threadIdx.x;
    int e0 = ob * OM_CHUNK;
    int e1 = min(e0 + OM_CHUNK, E);
    for (int i = tid; i < nmac; i += 256) scnt[i] = 0;
    __syncthreads();
    for (int e = e0 + tid; e < e1; e += 256) atomicAdd(scnt + dst[e], 1);
    __syncthreads();
    for (int i = tid; i < nmac; i += 256) {
        int c = scnt[i];
        sbase[i] = c ? atomicAdd(deg + i, c) : 0;
        scnt[i] = 0;
    }
    __syncthreads();
    for (int e = e0 + tid; e < e1; e += 256) {
        int d = dst[e];
        int slot = sbase[d] + atomicAdd(scnt + d, 1);
        if (slot < CAP_MAC)
            eb[(size_t)d * CAP_MAC + slot] = make_int2(src[e], __float_as_int(feat[e]));
    }
}

// seq+mo edges: op dsts (50k) -> low contention, direct atomics, 4 edges/thread
__device__ void bucket_sm_block(int sb, int Ea, int Eb,
                                const int* __restrict__ sa, const int* __restrict__ da,
                                const float* __restrict__ fa,
                                const int* __restrict__ sb_, const int* __restrict__ db,
                                const float* __restrict__ fb,
                                int* __restrict__ dega, int2* __restrict__ eba,
                                int* __restrict__ degb, int2* __restrict__ ebb)
{
    int tid = threadIdx.x;
#pragma unroll
    for (int r = 0; r < 4; r++) {
        int e = sb * SM_CHUNK + r * 256 + tid;
        if (e < Ea) {
            int s = sa[e], d = da[e];
            float f = fa[e];
            int slot = atomicAdd(dega + d, 1);
            if (slot < CAP_OP) eba[(size_t)d * CAP_OP + slot] = make_int2(s, __float_as_int(f));
        } else if (e < Ea + Eb) {
            int ee = e - Ea;
            int s = sb_[ee], d = db[ee];
            float f = fb[ee];
            int slot = atomicAdd(degb + d, 1);
            if (slot < CAP_OP) ebb[(size_t)d * CAP_OP + slot] = make_int2(s, __float_as_int(f));
        }
    }
}

// Bresenham interleave: the nb non-proj blocks (om buckets first, then mac proj,
// then sm buckets) are spread evenly among proj blocks so every wave mixes
// latency-bound bucket warps with FFMA2-heavy proj warps (no dead tail wave).
__global__ __launch_bounds__(256, 4) void k_prep(
    const float* h_op, const float* W_op_w, const float* W_op_b,
    const float* h_mac, const float* W_mac_w, const float* W_mac_b,
    const float* att_seq, const float* att_om, const float* att_mo,
    int nop, int nmac,
    int Eseq, int Emo, int Eom, int om_blocks, int total_blocks,
    const int* seq_src, const int* seq_dst, const float* feat_seq,
    const int* mo_src,  const int* mo_dst,  const float* feat_mo,
    const int* om_src,  const int* om_dst,  const float* feat_om,
    float* z, float* z_mac,
    float* asrc_seq, float* adst_seq, float* asrc_om, float* adst_mo,
    float* asrc_mo, float* adst_om,
    int* deg_seq, int2* eb_seq, int* deg_mo, int2* eb_mo, int* deg_om, int2* eb_om)
{
    __shared__ __align__(16) float pool[IN_OP * OUTF + 64 * IN_OP];  // 48 KB
    int bid = blockIdx.x;
    int nb = total_blocks - PRJ_BLOCKS;   // non-proj block count
    int before  = (int)(((long long)bid * nb) / total_blocks);
    int before1 = (int)(((long long)(bid + 1) * nb) / total_blocks);
    if (before1 > before) {
        int k = before;   // non-proj index: [om | mac | sm]
        if (k < om_blocks) {
            bucket_om_block(k, Eom, nmac, om_src, om_dst, feat_om, deg_om, eb_om, pool);
        } else if (k < om_blocks + MAC_BLOCKS) {
            proj_mac_block(k - om_blocks, h_mac, W_mac_w, W_mac_b, att_mo, att_om, nmac,
                           z_mac, asrc_mo, adst_om, pool);
        } else {
            bucket_sm_block(k - om_blocks - MAC_BLOCKS, Eseq, Emo,
                            seq_src, seq_dst, feat_seq,
                            mo_src, mo_dst, feat_mo,
                            deg_seq, eb_seq, deg_mo, eb_mo);
        }
    } else {
        proj_op_block(bid - before, h_op, W_op_w, W_op_b, att_seq, att_om, att_mo, nop,
                      z, asrc_seq, adst_seq, asrc_om, adst_mo, pool);
    }
}

// diagnostic spacer: shifts ncu's fixed capture index onto k_prep
__global__ void k_nop() {}

// ===================== final kernel =====================

// per-warp gather for one edge group of an op node; returns normalized contribution.
// soff holds precomputed row offsets (src*OUTF) -> 32-bit add in hot loop, no IMAD.wide.
__device__ __forceinline__ float4 gat_group(int d, const int* __restrict__ deg,
                                            const int2* __restrict__ eb,
                                            const float* __restrict__ asrc,
                                            const float* __restrict__ adst,
                                            const float* __restrict__ att,
                                            const float* __restrict__ z,
                                            float* salpha, int* soff,
                                            int lane, int head, int f0)
{
    float4 res = make_float4(0.f, 0.f, 0.f, 0.f);
    int cs = min(deg[d], CAP_OP);
    if (cs == 0) return res;
    float4 ad4 = *(const float4*)(adst + (size_t)d * HEADS);
    float af0 = att[2 * DK], af1 = att[ATT + 2 * DK], af2 = att[2 * ATT + 2 * DK],
          af3 = att[3 * ATT + 2 * DK];
    if (lane < cs) {
        int2 ed = eb[(size_t)d * CAP_OP + lane];
        float4 as = *(const float4*)(asrc + (size_t)ed.x * HEADS);
        float f = __int_as_float(ed.y);
        float4 al;
        al.x = lrexp(as.x + ad4.x + f * af0);
        al.y = lrexp(as.y + ad4.y + f * af1);
        al.z = lrexp(as.z + ad4.z + f * af2);
        al.w = lrexp(as.w + ad4.w + f * af3);
        *(float4*)(salpha + lane * 4) = al;
        soff[lane] = ed.x * OUTF;
    }
    __syncwarp();
    unsigned long long n0 = pack2(0.f, 0.f), n1 = n0;
    float den = 0.f;
#pragma unroll 4
    for (int i = 0; i < cs; i++) {
        float a = salpha[i * 4 + head];
        int o = soff[i];
        ulonglong2 zz = *(const ulonglong2*)(z + o + f0);
        unsigned long long aa = pack2(a, a);
        ffma2(n0, aa, zz.x); ffma2(n1, aa, zz.y);
        den += a;
    }
    __syncwarp();
    float inv = 1.f / (den + EPS);
    float x0, x1, x2, x3;
    unpack2(n0, x0, x1);
    unpack2(n1, x2, x3);
    res.x = x0 * inv; res.y = x1 * inv; res.z = x2 * inv; res.w = x3 * inv;
    return res;
}

__device__ __forceinline__ void ln_elu_store(float4 v, const float* g, const float* b,
                                             float* out, int f0)
{
    float s0 = wallred(v.x + v.y + v.z + v.w);
    float mu = s0 * (1.f / OUTF);
    float d0 = v.x - mu, d1 = v.y - mu, d2 = v.z - mu, d3 = v.w - mu;
    float var = wallred(d0 * d0 + d1 * d1 + d2 * d2 + d3 * d3);
    float rs = rsqrtf(var * (1.f / OUTF) + 1e-5f);
    float4 gg = *(const float4*)(g + f0);
    float4 bb = *(const float4*)(b + f0);
    float4 y;
    y.x = d0 * rs * gg.x + bb.x;
    y.y = d1 * rs * gg.y + bb.y;
    y.z = d2 * rs * gg.z + bb.z;
    y.w = d3 * rs * gg.w + bb.w;
    y.x = y.x > 0.f ? y.x : __expf(y.x) - 1.f;
    y.y = y.y > 0.f ? y.y : __expf(y.y) - 1.f;
    y.z = y.z > 0.f ? y.z : __expf(y.z) - 1.f;
    y.w = y.w > 0.f ? y.w : __expf(y.w) - 1.f;
    *(float4*)(out + f0) = y;
}

__global__ __launch_bounds__(256) void k_final(
    int nmac, int nop,
    const int* __restrict__ deg_om, const int2* __restrict__ eb_om,
    const float* __restrict__ asrc_om, const float* __restrict__ adst_om,
    const float* __restrict__ att_om,
    const int* __restrict__ deg_seq, const int2* __restrict__ eb_seq,
    const int* __restrict__ deg_mo,  const int2* __restrict__ eb_mo,
    const float* __restrict__ asrc_seq, const float* __restrict__ adst_seq,
    const float* __restrict__ asrc_mo,  const float* __restrict__ adst_mo,
    const float* __restrict__ att_seq, const float* __restrict__ att_mo,
    const float* __restrict__ z,
    const float* __restrict__ ln_op_g, const float* __restrict__ ln_op_b,
    const float* __restrict__ ln_mac_g, const float* __restrict__ ln_mac_b,
    float* __restrict__ out)
{
    __shared__ __align__(16) float pool[2880];
    int tid = threadIdx.x;
    int w = tid >> 5, lane = tid & 31;
    int head = lane >> 3;
    int f0 = lane * 4;

    if (blockIdx.x < (unsigned)nmac) {
        // ---- mac node (block per node; long blocks scheduled first) ----
        int d = blockIdx.x;
        float* salpha = pool;                 // 320*4
        int*   soff   = (int*)(pool + 1280);  // 320
        float* snum   = pool + 1600;          // 8*32*4
        float* sden   = pool + 2624;          // 8*32

        int c = min(deg_om[d], CAP_MAC);
        float4 ad4 = *(const float4*)(adst_om + (size_t)d * HEADS);
        float af0 = att_om[2 * DK], af1 = att_om[ATT + 2 * DK],
              af2 = att_om[2 * ATT + 2 * DK], af3 = att_om[3 * ATT + 2 * DK];
        for (int e = tid; e < c; e += 256) {
            int2 ed = eb_om[(size_t)d * CAP_MAC + e];
            float4 as = *(const float4*)(asrc_om + (size_t)ed.x * HEADS);
            float f = __int_as_float(ed.y);
            float4 al;
            al.x = lrexp(as.x + ad4.x + f * af0);
            al.y = lrexp(as.y + ad4.y + f * af1);
            al.z = lrexp(as.z + ad4.z + f * af2);
            al.w = lrexp(as.w + ad4.w + f * af3);
            *(float4*)(salpha + e * 4) = al;
            soff[e] = ed.x * OUTF;            // op-row offset, fits in int
        }
        __syncthreads();
        unsigned long long q0 = pack2(0.f, 0.f), q1 = q0;
        float den = 0.f;
#pragma unroll 2
        for (int i = w; i < c; i += 8) {
            float a = salpha[i * 4 + head];
            int o = soff[i];
            ulonglong2 zz = *(const ulonglong2*)(z + o + f0);
            unsigned long long aa = pack2(a, a);
            ffma2(q0, aa, zz.x); ffma2(q1, aa, zz.y);
            den += a;
        }
        float4 num;
        unpack2(q0, num.x, num.y);
        unpack2(q1, num.z, num.w);
        *(float4*)(snum + (w * 32 + lane) * 4) = num;
        sden[w * 32 + lane] = den;
        __syncthreads();
        if (w != 0) return;
        float4 r = *(const float4*)(snum + lane * 4);
        float dn = sden[lane];
#pragma unroll
        for (int ww = 1; ww < 8; ww++) {
            float4 t = *(const float4*)(snum + (ww * 32 + lane) * 4);
            r.x += t.x; r.y += t.y; r.z += t.z; r.w += t.w;
            dn += sden[ww * 32 + lane];
        }
        float inv = 1.f / (dn + EPS);
        float4 v = *(const float4*)(z + ((size_t)N_OP_MAX + d) * OUTF + f0);  // residual
        v.x += r.x * inv; v.y += r.y * inv; v.z += r.z * inv; v.w += r.w * inv;
        ln_elu_store(v, ln_mac_g, ln_mac_b, out + ((size_t)nop + d) * OUTF, f0);
    } else {
        // ---- op nodes (warp per node) ----
        int d = (blockIdx.x - nmac) * 8 + w;
        if (d >= nop) return;
        float* salpha = pool + w * 160;        // 128 alpha + 32 offsets per warp
        int*   soff   = (int*)(salpha + 128);

        float4 v = *(const float4*)(z + (size_t)d * OUTF + f0);  // residual
        float4 c1 = gat_group(d, deg_seq, eb_seq, asrc_seq, adst_seq, att_seq,
                              z, salpha, soff, lane, head, f0);
        v.x += c1.x; v.y += c1.y; v.z += c1.z; v.w += c1.w;
        float4 c2 = gat_group(d, deg_mo, eb_mo, asrc_mo, adst_mo, att_mo,
                              z + (size_t)N_OP_MAX * OUTF, salpha, soff, lane, head, f0);
        v.x += c2.x; v.y += c2.y; v.z += c2.z; v.w += c2.w;
        ln_elu_store(v, ln_op_g, ln_op_b, out + (size_t)d * OUTF, f0);
    }
}

// ---------------- launch ----------------
extern "C" void kernel_launch(void* const* d_in, const int* in_sizes, int n_in,
                              void* d_out, int out_size)
{
    const float* h_op     = (const float*)d_in[0];
    const float* h_mac    = (const float*)d_in[1];
    const int*   seq_src  = (const int*)d_in[2];
    const int*   seq_dst  = (const int*)d_in[3];
    const int*   om_src   = (const int*)d_in[4];
    const int*   om_dst   = (const int*)d_in[5];
    const int*   mo_src   = (const int*)d_in[6];
    const int*   mo_dst   = (const int*)d_in[7];
    const float* feat_seq = (const float*)d_in[8];
    const float* feat_om  = (const float*)d_in[9];
    const float* feat_mo  = (const float*)d_in[10];
    const float* W_op_w   = (const float*)d_in[11];
    const float* W_op_b   = (const float*)d_in[12];
    const float* W_mac_w  = (const float*)d_in[13];
    const float* W_mac_b  = (const float*)d_in[14];
    const float* att_seq  = (const float*)d_in[15];
    const float* att_om   = (const float*)d_in[16];
    const float* att_mo   = (const float*)d_in[17];
    const float* ln_op_g  = (const float*)d_in[18];
    const float* ln_op_b  = (const float*)d_in[19];
    const float* ln_mac_g = (const float*)d_in[20];
    const float* ln_mac_b = (const float*)d_in[21];
    float* out = (float*)d_out;

    int nop  = in_sizes[0] / IN_OP;
    int nmac = in_sizes[1] / IN_MAC;
    int Eseq = in_sizes[2];
    int Eom  = in_sizes[4];
    int Emo  = in_sizes[6];

    float *p_z;
    float *p_asrc_seq, *p_adst_seq, *p_asrc_om, *p_adst_mo, *p_asrc_mo, *p_adst_om;
    int2 *p_eb_seq, *p_eb_mo, *p_eb_om;
    int *p_deg;
    cudaGetSymbolAddress((void**)&p_z,        g_z);
    cudaGetSymbolAddress((void**)&p_asrc_seq, g_asrc_seq);
    cudaGetSymbolAddress((void**)&p_adst_seq, g_adst_seq);
    cudaGetSymbolAddress((void**)&p_asrc_om,  g_asrc_om);
    cudaGetSymbolAddress((void**)&p_adst_mo,  g_adst_mo);
    cudaGetSymbolAddress((void**)&p_asrc_mo,  g_asrc_mo);
    cudaGetSymbolAddress((void**)&p_adst_om,  g_adst_om);
    cudaGetSymbolAddress((void**)&p_eb_seq,   g_eb_seq);
    cudaGetSymbolAddress((void**)&p_eb_mo,    g_eb_mo);
    cudaGetSymbolAddress((void**)&p_eb_om,    g_eb_om);
    cudaGetSymbolAddress((void**)&p_deg,      g_deg);

    int* p_deg_seq = p_deg + DEG_SEQ_OFF;
    int* p_deg_mo  = p_deg + DEG_MO_OFF;
    int* p_deg_om  = p_deg + DEG_OM_OFF;
    float* p_z_mac = p_z + (size_t)N_OP_MAX * OUTF;

    cudaMemsetAsync(p_deg, 0, DEG_TOT * sizeof(int));

    int om_blocks = (Eom + OM_CHUNK - 1) / OM_CHUNK;
    int sm_blocks = (Eseq + Emo + SM_CHUNK - 1) / SM_CHUNK;
    int prep_grid = PRJ_BLOCKS + MAC_BLOCKS + om_blocks + sm_blocks;
    k_prep<<<prep_grid, 256>>>(
        h_op, W_op_w, W_op_b, h_mac, W_mac_w, W_mac_b,
        att_seq, att_om, att_mo, nop, nmac,
        Eseq, Emo, Eom, om_blocks, prep_grid,
        seq_src, seq_dst, feat_seq,
        mo_src, mo_dst, feat_mo,
        om_src, om_dst, feat_om,
        p_z, p_z_mac,
        p_asrc_seq, p_adst_seq, p_asrc_om, p_adst_mo,
        p_asrc_mo, p_adst_om,
        p_deg_seq, p_eb_seq, p_deg_mo, p_eb_mo, p_deg_om, p_eb_om);

    k_nop<<<1, 1>>>();   // spacer: keeps ncu capture slot on k_prep

    int final_grid = nmac + (nop + 7) / 8;
    k_final<<<final_grid, 256>>>(
        nmac, nop,
        p_deg_om, p_eb_om, p_asrc_om, p_adst_om, att_om,
        p_deg_seq, p_eb_seq, p_deg_mo, p_eb_mo,
        p_asrc_seq, p_adst_seq, p_asrc_mo, p_adst_mo,
        att_seq, att_mo,
        p_z,
        ln_op_g, ln_op_b, ln_mac_g, ln_mac_b,
        out);
}